// round 8
// baseline (speedup 1.0000x reference)
#include <cuda_runtime.h>
#include <math.h>
#include <stdint.h>

// ---------------------------------------------------------------------------
// CrossModalAttention on sm_103 — tf32 mma.sync, fused P-write + context:
//   Q/K/V projections : tf32 HMMA GEMM (A@B^T), in-frag RNA, bias, RNA out
//   VT transpose      : per-head V^T (k-contiguous) for ctx mma
//   rowsum            : S via mma (128x128 tiles), exp, per-CTA partials -> PS
//   fused_pctx        : per (bh,128-q strip): invl from PS; loop 64-key
//                       chunks: recompute S (identical frag math), P =
//                       exp(s*t)*invl -> gmem ONCE, rna(P)->SMEM,
//                       ctx += P @ VT^T. 102KB smem -> 2 CTAs/SM.
//   out projection    : tf32 HMMA GEMM + bias
//   residual + LayerNorm (fp32)
// Shapes fixed: B=2, S=2048, HIDDEN=1024, HEADS=16, HDIM=64.
// ---------------------------------------------------------------------------

#define HIDDEN_ 1024
#define HEADS_  16
#define HDIM_   64
#define BATCH_  2
#define SEQ_    2048
#define MTOT_   (BATCH_*SEQ_)            // 4096
#define NROWS_  (BATCH_*HEADS_*SEQ_)     // 65536 attention rows

static const long long LN_N  = (long long)MTOT_ * HIDDEN_;               // 4,194,304
static const long long ATT_N = (long long)BATCH_ * HEADS_ * SEQ_ * SEQ_; // 134,217,728

// Scratch (__device__ globals: allocation-free rule)
__device__ float g_Q  [(size_t)MTOT_ * HIDDEN_];
__device__ float g_K  [(size_t)MTOT_ * HIDDEN_];
__device__ float g_V  [(size_t)MTOT_ * HIDDEN_];
__device__ float g_VT [(size_t)BATCH_ * HEADS_ * HDIM_ * SEQ_];
__device__ float g_ctx[(size_t)MTOT_ * HIDDEN_];
__device__ float g_o  [(size_t)MTOT_ * HIDDEN_];
__device__ float g_PS [(size_t)NROWS_ * 16];                    // partial sums
__device__ float g_Pfb[(size_t)BATCH_ * HEADS_ * SEQ_ * SEQ_];  // P fallback

// ---------------------------------------------------------------------------
// PTX helpers (sm_80+ portable)
// ---------------------------------------------------------------------------
__device__ __forceinline__ uint32_t smem_u32(const void* p) {
    return (uint32_t)__cvta_generic_to_shared(p);
}
__device__ __forceinline__ float rna_tf32(float x) {
    uint32_t y;
    asm("cvt.rna.tf32.f32 %0, %1;" : "=r"(y) : "f"(x));
    return __uint_as_float(y);
}
__device__ __forceinline__ void cp_async16(uint32_t dst, const void* src) {
    asm volatile("cp.async.cg.shared.global [%0], [%1], 16;" :: "r"(dst), "l"(src));
}
__device__ __forceinline__ void cp_commit() { asm volatile("cp.async.commit_group;" ::: "memory"); }
template <int N>
__device__ __forceinline__ void cp_wait_group() {
    asm volatile("cp.async.wait_group %0;" :: "n"(N) : "memory");
}
__device__ __forceinline__ void cp_wait_all_() {
    asm volatile("cp.async.wait_all;" ::: "memory");
}
__device__ __forceinline__ void st_cs_v2(float* p, float a, float b) {
    asm volatile("st.global.cs.v2.f32 [%0], {%1,%2};" :: "l"(p), "f"(a), "f"(b) : "memory");
}
// D += A*B, m16n8k8 tf32 (HMMA on tensor pipe)
__device__ __forceinline__ void mma1688(float* d, const uint32_t* a, const uint32_t* b) {
    asm volatile(
        "mma.sync.aligned.m16n8k8.row.col.f32.tf32.tf32.f32 "
        "{%0,%1,%2,%3}, {%4,%5,%6,%7}, {%8,%9}, {%0,%1,%2,%3};"
        : "+f"(d[0]), "+f"(d[1]), "+f"(d[2]), "+f"(d[3])
        : "r"(a[0]), "r"(a[1]), "r"(a[2]), "r"(a[3]), "r"(b[0]), "r"(b[1]));
}

// ---------------------------------------------------------------------------
// tf32 mma.sync GEMM:  C[m,n] = sum_k A[m,k]*B[n,k] (+bias[n])
// RA/RB: RNA-round fragments on load. ROUND: RNA-round outputs.
// BM=128, BN=128, BK=32 floats. 256 threads = 8 warps (2x4).
// ---------------------------------------------------------------------------
template <bool RA, bool RB, bool ROUND>
__global__ void __launch_bounds__(256)
tc_gemm(const float* __restrict__ A, const float* __restrict__ Bm,
        const float* __restrict__ bias, float* __restrict__ C,
        int K, int lda, int ldb, int ldc)
{
    constexpr int LDS_ = 36;
    constexpr int AS_STAGE = 128 * LDS_;
    constexpr int BS_STAGE = 128 * LDS_;

    extern __shared__ float sm[];
    float* As = sm;
    float* Bs = sm + 2 * AS_STAGE;

    const int tid  = threadIdx.x;
    const int warp = tid >> 5;
    const int lane = tid & 31;
    const int wr = warp & 1, wc = warp >> 1;
    const int g = lane >> 2, t = lane & 3;
    const int row0 = blockIdx.y * 128;
    const int col0 = blockIdx.x * 128;

    float acc[4][4][4];
#pragma unroll
    for (int i = 0; i < 4; ++i)
#pragma unroll
        for (int j = 0; j < 4; ++j)
#pragma unroll
            for (int q = 0; q < 4; ++q) acc[i][j][q] = 0.0f;

    auto load_tile = [&](int kt) {
        const int st = kt & 1;
        const float* Ag = A + (size_t)row0 * lda + kt * 32;
        float* Ad = As + st * AS_STAGE;
#pragma unroll
        for (int i = 0; i < 4; ++i) {
            int id = tid + i * 256;
            int r = id >> 3, c = id & 7;
            cp_async16(smem_u32(Ad + r * LDS_ + c * 4), Ag + (size_t)r * lda + c * 4);
        }
        const float* Bg = Bm + (size_t)col0 * ldb + kt * 32;
        float* Bd = Bs + st * BS_STAGE;
#pragma unroll
        for (int i = 0; i < 4; ++i) {
            int id = tid + i * 256;
            int r = id >> 3, c = id & 7;
            cp_async16(smem_u32(Bd + r * LDS_ + c * 4), Bg + (size_t)r * ldb + c * 4);
        }
        cp_commit();
    };

    const int T = K >> 5;
    load_tile(0);
    for (int kt = 0; kt < T; ++kt) {
        if (kt + 1 < T) { load_tile(kt + 1); cp_wait_group<1>(); }
        else            { cp_wait_group<0>(); }
        __syncthreads();

        const float* Ab = As + (kt & 1) * AS_STAGE + (wr * 64) * LDS_;
        const float* Bb = Bs + (kt & 1) * BS_STAGE + (wc * 32) * LDS_;
#pragma unroll
        for (int s = 0; s < 4; ++s) {
            const int k0 = s * 8;
            uint32_t a[4][4], b[4][2];
#pragma unroll
            for (int i = 0; i < 4; ++i) {
                const float* ap = Ab + (i * 16 + g) * LDS_ + k0 + t;
                float a0 = ap[0], a1 = ap[8 * LDS_], a2 = ap[4], a3 = ap[8 * LDS_ + 4];
                if (RA) { a0 = rna_tf32(a0); a1 = rna_tf32(a1); a2 = rna_tf32(a2); a3 = rna_tf32(a3); }
                a[i][0] = __float_as_uint(a0);
                a[i][1] = __float_as_uint(a1);
                a[i][2] = __float_as_uint(a2);
                a[i][3] = __float_as_uint(a3);
            }
#pragma unroll
            for (int j = 0; j < 4; ++j) {
                const float* bp = Bb + (j * 8 + g) * LDS_ + k0 + t;
                float b0 = bp[0], b1 = bp[4];
                if (RB) { b0 = rna_tf32(b0); b1 = rna_tf32(b1); }
                b[j][0] = __float_as_uint(b0);
                b[j][1] = __float_as_uint(b1);
            }
#pragma unroll
            for (int i = 0; i < 4; ++i)
#pragma unroll
                for (int j = 0; j < 4; ++j)
                    mma1688(acc[i][j], a[i], b[j]);
        }
        __syncthreads();
    }

#pragma unroll
    for (int i = 0; i < 4; ++i) {
#pragma unroll
        for (int j = 0; j < 4; ++j) {
            const int r = row0 + wr * 64 + i * 16 + g;
            const int c = col0 + wc * 32 + j * 8 + 2 * t;
            float2 v0 = make_float2(acc[i][j][0], acc[i][j][1]);
            float2 v1 = make_float2(acc[i][j][2], acc[i][j][3]);
            if (bias) {
                const float bx = bias[c], by = bias[c + 1];
                v0.x += bx; v0.y += by;
                v1.x += bx; v1.y += by;
            }
            if (ROUND) {
                v0.x = rna_tf32(v0.x); v0.y = rna_tf32(v0.y);
                v1.x = rna_tf32(v1.x); v1.y = rna_tf32(v1.y);
            }
            *(float2*)&C[(size_t)r * ldc + c]       = v0;
            *(float2*)&C[(size_t)(r + 8) * ldc + c] = v1;
        }
    }
}

// ---------------------------------------------------------------------------
// Per-head V transpose: VT[bh][d][k] = V[b*SEQ+k][h*HDIM+d]
// ---------------------------------------------------------------------------
__global__ void __launch_bounds__(256)
transpose_v_kernel(const float* __restrict__ V, float* __restrict__ VT)
{
    __shared__ float t[32][33];
    const int bh = blockIdx.z;
    const int b = bh / HEADS_, h = bh % HEADS_;
    const int k0 = blockIdx.x * 32;
    const int d0 = blockIdx.y * 32;
    const int tx = threadIdx.x & 31;
    const int ty = threadIdx.x >> 5;
    const float* src = V + (size_t)(b * SEQ_) * HIDDEN_ + h * HDIM_;
#pragma unroll
    for (int j = 0; j < 4; ++j)
        t[ty + 8 * j][tx] = src[(size_t)(k0 + ty + 8 * j) * HIDDEN_ + d0 + tx];
    __syncthreads();
    float* dst = VT + (size_t)bh * HDIM_ * SEQ_;
#pragma unroll
    for (int j = 0; j < 4; ++j)
        dst[(size_t)(d0 + ty + 8 * j) * SEQ_ + k0 + tx] = t[tx][ty + 8 * j];
}

// ---------------------------------------------------------------------------
// Row sums: per CTA = 128x128 S tile of one (bh); NO gmem tensor write.
// Per-row partial sums of exp(S*temp) -> PS[row][bx].
// ---------------------------------------------------------------------------
__global__ void __launch_bounds__(256)
rowsum_kernel(const float* __restrict__ Q, const float* __restrict__ K,
              float* __restrict__ PS, const float* __restrict__ tptr)
{
    constexpr int LDP = 68;
    extern __shared__ float sm[];
    float* Qs = sm;                 // 128*68
    float* Ks = sm + 128 * LDP;     // 128*68
    __shared__ float red[512];

    const int bx = blockIdx.x;      // key block (0..15)
    const int by = blockIdx.y;      // query block (0..15)
    const int bh = blockIdx.z;
    const int b = bh >> 4, h = bh & 15;
    const int tid = threadIdx.x, lane = tid & 31, warp = tid >> 5;
    const int wr = warp & 1, wc = warp >> 1;
    const int g = lane >> 2, t = lane & 3;
    const float temp = *tptr;

    const float* Qg = Q + ((size_t)(b * SEQ_) + by * 128) * HIDDEN_ + h * HDIM_;
    const float* Kg = K + ((size_t)(b * SEQ_) + bx * 128) * HIDDEN_ + h * HDIM_;

#pragma unroll
    for (int i = 0; i < 8; ++i) {
        int id = tid + i * 256;
        int r = id >> 4, c = id & 15;
        cp_async16(smem_u32(Qs + r * LDP + c * 4), Qg + (size_t)r * HIDDEN_ + c * 4);
    }
#pragma unroll
    for (int i = 0; i < 8; ++i) {
        int id = tid + i * 256;
        int r = id >> 4, c = id & 15;
        cp_async16(smem_u32(Ks + r * LDP + c * 4), Kg + (size_t)r * HIDDEN_ + c * 4);
    }
    cp_commit();
    cp_wait_group<0>();
    __syncthreads();

    float acc[4][4][4];
#pragma unroll
    for (int i = 0; i < 4; ++i)
#pragma unroll
        for (int j = 0; j < 4; ++j)
#pragma unroll
            for (int q = 0; q < 4; ++q) acc[i][j][q] = 0.0f;

#pragma unroll
    for (int s = 0; s < 8; ++s) {
        const int k0 = s * 8;
        uint32_t a[4][4], bf[4][2];
#pragma unroll
        for (int i = 0; i < 4; ++i) {
            const float* ap = Qs + (wr * 64 + i * 16 + g) * LDP + k0 + t;
            a[i][0] = __float_as_uint(ap[0]);
            a[i][1] = __float_as_uint(ap[8 * LDP]);
            a[i][2] = __float_as_uint(ap[4]);
            a[i][3] = __float_as_uint(ap[8 * LDP + 4]);
        }
#pragma unroll
        for (int j = 0; j < 4; ++j) {
            const float* bp = Ks + (wc * 32 + j * 8 + g) * LDP + k0 + t;
            bf[j][0] = __float_as_uint(bp[0]);
            bf[j][1] = __float_as_uint(bp[4]);
        }
#pragma unroll
        for (int i = 0; i < 4; ++i)
#pragma unroll
            for (int j = 0; j < 4; ++j)
                mma1688(acc[i][j], a[i], bf[j]);
    }

    float rs0[4], rs1[4];
#pragma unroll
    for (int i = 0; i < 4; ++i) { rs0[i] = 0.f; rs1[i] = 0.f; }
#pragma unroll
    for (int i = 0; i < 4; ++i) {
#pragma unroll
        for (int j = 0; j < 4; ++j) {
            rs0[i] += __expf(acc[i][j][0] * temp) + __expf(acc[i][j][1] * temp);
            rs1[i] += __expf(acc[i][j][2] * temp) + __expf(acc[i][j][3] * temp);
        }
    }
#pragma unroll
    for (int i = 0; i < 4; ++i) {
        rs0[i] += __shfl_xor_sync(0xffffffffu, rs0[i], 1);
        rs0[i] += __shfl_xor_sync(0xffffffffu, rs0[i], 2);
        rs1[i] += __shfl_xor_sync(0xffffffffu, rs1[i], 1);
        rs1[i] += __shfl_xor_sync(0xffffffffu, rs1[i], 2);
    }
    if (t == 0) {
#pragma unroll
        for (int i = 0; i < 4; ++i) {
            red[wc * 128 + wr * 64 + i * 16 + g]     = rs0[i];
            red[wc * 128 + wr * 64 + i * 16 + g + 8] = rs1[i];
        }
    }
    __syncthreads();
    if (tid < 128) {
        float s = red[tid] + red[128 + tid] + red[256 + tid] + red[384 + tid];
        PS[((size_t)bh * SEQ_ + by * 128 + tid) * 16 + bx] = s;
    }
}

// ---------------------------------------------------------------------------
// fused_pctx: per CTA = (bh, 128-q strip). Loop 32 key-chunks of 64.
// Prologue: invl from PS. Per chunk: S mma (identical frag math as rowsum),
// P = exp(s*temp)*invl -> gmem (ONLY P pass), rna(P)->Ps, ctx += Ps@Vs^T.
// smem: Qs 128x68 + Ks 64x68 + Vs 64x68 + Ps 128x68 = 102KB -> 2 CTA/SM.
// K(kt+1) prefetched after S-mma (overlaps epilogue+ctx); V(kt+1) after.
// ---------------------------------------------------------------------------
__global__ void __launch_bounds__(256)
fused_pctx_kernel(const float* __restrict__ Q, const float* __restrict__ K,
                  const float* __restrict__ VT, const float* __restrict__ PS,
                  float* __restrict__ P, float* __restrict__ CTX,
                  const float* __restrict__ tptr)
{
    constexpr int LDP = 68;
    extern __shared__ float sm[];
    float* Qs = sm;                    // 128*68 = 8704
    float* Ks = sm + 8704;             // 64*68  = 4352
    float* Vs = sm + 13056;            // 64*68  = 4352
    float* Ps = sm + 17408;            // 128*68 = 8704  (total 26112 fl = 102KB)
    __shared__ float s_inv[128];

    const int strip = blockIdx.x;      // 0..15 (128 q-rows)
    const int bh = blockIdx.y;
    const int b = bh >> 4, h = bh & 15;
    const int tid = threadIdx.x, lane = tid & 31, warp = tid >> 5;
    const int wr = warp & 1, wc = warp >> 1;
    const int g = lane >> 2, t = lane & 3;
    const float temp = *tptr;

    const float* Qg = Q + ((size_t)(b * SEQ_) + strip * 128) * HIDDEN_ + h * HDIM_;
    const float* Kg = K + (size_t)(b * SEQ_) * HIDDEN_ + h * HDIM_;
    const float* Vg = VT + (size_t)bh * HDIM_ * SEQ_;
    float*       Pg = P + ((size_t)bh * SEQ_ + strip * 128) * SEQ_;
    float*       Cg = CTX + ((size_t)(b * SEQ_) + strip * 128) * HIDDEN_ + h * HDIM_;

    // invl: 128 rows, sum 16 partials each
    if (tid < 128) {
        const float* ps = PS + ((size_t)bh * SEQ_ + strip * 128 + tid) * 16;
        float s = 0.f;
#pragma unroll
        for (int k = 0; k < 16; ++k) s += ps[k];
        s_inv[tid] = 1.0f / s;
    }

    // Q strip 128x64 -> SMEM
#pragma unroll
    for (int i = 0; i < 8; ++i) {
        int id = tid + i * 256;
        int r = id >> 4, c = id & 15;
        cp_async16(smem_u32(Qs + r * LDP + c * 4), Qg + (size_t)r * HIDDEN_ + c * 4);
    }

    auto loadK = [&](int kt) {         // 64 keys x 64 d
        const float* ks = Kg + (size_t)(kt * 64) * HIDDEN_;
#pragma unroll
        for (int i = 0; i < 4; ++i) {
            int id = tid + i * 256;
            int r = id >> 4, c = id & 15;
            cp_async16(smem_u32(Ks + r * LDP + c * 4), ks + (size_t)r * HIDDEN_ + c * 4);
        }
        cp_commit();
    };
    auto loadV = [&](int kt) {         // 64 d x 64 k
        const float* vs = Vg + kt * 64;
#pragma unroll
        for (int i = 0; i < 4; ++i) {
            int id = tid + i * 256;
            int r = id >> 4, c = id & 15;
            cp_async16(smem_u32(Vs + r * LDP + c * 4), vs + (size_t)r * SEQ_ + c * 4);
        }
        cp_commit();
    };

    loadK(0);
    loadV(0);
    cp_wait_all_();
    __syncthreads();                   // Q, K0, V0, s_inv all ready

    float linv[4][2];
#pragma unroll
    for (int i = 0; i < 4; ++i) {
        linv[i][0] = s_inv[wr * 64 + i * 16 + g];
        linv[i][1] = s_inv[wr * 64 + i * 16 + g + 8];
    }

    float ctx[4][2][4];
#pragma unroll
    for (int i = 0; i < 4; ++i)
#pragma unroll
        for (int j = 0; j < 2; ++j)
#pragma unroll
            for (int q = 0; q < 4; ++q) ctx[i][j][q] = 0.f;

    for (int kt = 0; kt < 32; ++kt) {
        // --- S mma: 128q x 64k, K=64d (same frag math as rowsum)
        float acc[4][2][4];
#pragma unroll
        for (int i = 0; i < 4; ++i)
#pragma unroll
            for (int j = 0; j < 2; ++j)
#pragma unroll
                for (int q = 0; q < 4; ++q) acc[i][j][q] = 0.f;
#pragma unroll
        for (int s = 0; s < 8; ++s) {
            const int k0 = s * 8;
            uint32_t a[4][4], bf[2][2];
#pragma unroll
            for (int i = 0; i < 4; ++i) {
                const float* ap = Qs + (wr * 64 + i * 16 + g) * LDP + k0 + t;
                a[i][0] = __float_as_uint(ap[0]);
                a[i][1] = __float_as_uint(ap[8 * LDP]);
                a[i][2] = __float_as_uint(ap[4]);
                a[i][3] = __float_as_uint(ap[8 * LDP + 4]);
            }
#pragma unroll
            for (int j = 0; j < 2; ++j) {
                const float* bp = Ks + (wc * 16 + j * 8 + g) * LDP + k0 + t;
                bf[j][0] = __float_as_uint(bp[0]);
                bf[j][1] = __float_as_uint(bp[4]);
            }
#pragma unroll
            for (int i = 0; i < 4; ++i)
#pragma unroll
                for (int j = 0; j < 2; ++j)
                    mma1688(acc[i][j], a[i], bf[j]);
        }
        __syncthreads();               // all warps done with Ks
        if (kt + 1 < 32) loadK(kt + 1);  // overlaps epilogue + ctx mma

        // --- P = exp(s*temp)*invl -> gmem + rna -> Ps
#pragma unroll
        for (int i = 0; i < 4; ++i) {
            const int rA = wr * 64 + i * 16 + g;
#pragma unroll
            for (int j = 0; j < 2; ++j) {
                const int c = wc * 16 + j * 8 + 2 * t;
                float p0 = __expf(acc[i][j][0] * temp) * linv[i][0];
                float p1 = __expf(acc[i][j][1] * temp) * linv[i][0];
                float p2 = __expf(acc[i][j][2] * temp) * linv[i][1];
                float p3 = __expf(acc[i][j][3] * temp) * linv[i][1];
                st_cs_v2(Pg + (size_t)rA * SEQ_ + kt * 64 + c, p0, p1);
                st_cs_v2(Pg + (size_t)(rA + 8) * SEQ_ + kt * 64 + c, p2, p3);
                *(float2*)(Ps + rA * LDP + c)       = make_float2(rna_tf32(p0), rna_tf32(p1));
                *(float2*)(Ps + (rA + 8) * LDP + c) = make_float2(rna_tf32(p2), rna_tf32(p3));
            }
        }
        __syncthreads();               // Ps visible

        // --- ctx += Ps(128q x 64k) @ Vs(64d x 64k)^T
#pragma unroll
        for (int s = 0; s < 8; ++s) {
            const int k0 = s * 8;
            uint32_t a[4][4], bf[2][2];
#pragma unroll
            for (int i = 0; i < 4; ++i) {
                const float* ap = Ps + (wr * 64 + i * 16 + g) * LDP + k0 + t;
                a[i][0] = __float_as_uint(ap[0]);
                a[i][1] = __float_as_uint(ap[8 * LDP]);
                a[i][2] = __float_as_uint(ap[4]);
                a[i][3] = __float_as_uint(ap[8 * LDP + 4]);
            }
#pragma unroll
            for (int j = 0; j < 2; ++j) {
                const float* bp = Vs + (wc * 16 + j * 8 + g) * LDP + k0 + t;
                bf[j][0] = __float_as_uint(bp[0]);
                bf[j][1] = __float_as_uint(bp[4]);
            }
#pragma unroll
            for (int i = 0; i < 4; ++i)
#pragma unroll
                for (int j = 0; j < 2; ++j)
                    mma1688(ctx[i][j], a[i], bf[j]);
        }
        __syncthreads();               // Vs/Ps free
        if (kt + 1 < 32) loadV(kt + 1);
        cp_wait_all_();                // K(kt+1) + V(kt+1) arrived
        __syncthreads();               // tiles ready for next iter
    }

    // write ctx (RNA: feeds out-projection GEMM)
#pragma unroll
    for (int i = 0; i < 4; ++i) {
        const int rA = wr * 64 + i * 16 + g;
#pragma unroll
        for (int j = 0; j < 2; ++j) {
            const int c = wc * 16 + j * 8 + 2 * t;
            *(float2*)(Cg + (size_t)rA * HIDDEN_ + c) =
                make_float2(rna_tf32(ctx[i][j][0]), rna_tf32(ctx[i][j][1]));
            *(float2*)(Cg + (size_t)(rA + 8) * HIDDEN_ + c) =
                make_float2(rna_tf32(ctx[i][j][2]), rna_tf32(ctx[i][j][3]));
        }
    }
}

// ---------------------------------------------------------------------------
// Residual + LayerNorm (fp32)
// ---------------------------------------------------------------------------
__global__ void __launch_bounds__(256)
ln_kernel(const float* __restrict__ o, const float* __restrict__ resid,
          const float* __restrict__ gamma, const float* __restrict__ beta,
          float* __restrict__ out)
{
    __shared__ float red1[8], red2[8];
    __shared__ float bmean, binv;

    const size_t row = blockIdx.x;
    const int tid = threadIdx.x;
    const int lane = tid & 31, wid = tid >> 5;
    const float* po = o + row * HIDDEN_;
    const float* pr = resid + row * HIDDEN_;

    float x[4];
    float s = 0.0f, s2 = 0.0f;
#pragma unroll
    for (int u = 0; u < 4; ++u) {
        const int idx = tid + 256 * u;
        x[u] = po[idx] + pr[idx];
        s += x[u];
        s2 += x[u] * x[u];
    }
#pragma unroll
    for (int of = 16; of; of >>= 1) {
        s  += __shfl_xor_sync(0xffffffffu, s,  of);
        s2 += __shfl_xor_sync(0xffffffffu, s2, of);
    }
    if (lane == 0) { red1[wid] = s; red2[wid] = s2; }
    __syncthreads();
    if (wid == 0) {
        float t1 = (lane < 8) ? red1[lane] : 0.0f;
        float t2 = (lane < 8) ? red2[lane] : 0.0f;
#pragma unroll
        for (int of = 16; of; of >>= 1) {
            t1 += __shfl_xor_sync(0xffffffffu, t1, of);
            t2 += __shfl_xor_sync(0xffffffffu, t2, of);
        }
        if (lane == 0) {
            const float mean = t1 * (1.0f / HIDDEN_);
            const float var  = t2 * (1.0f / HIDDEN_) - mean * mean;
            bmean = mean;
            binv  = rsqrtf(var + 1e-5f);
        }
    }
    __syncthreads();
    const float mean = bmean, inv = binv;
#pragma unroll
    for (int u = 0; u < 4; ++u) {
        const int idx = tid + 256 * u;
        out[row * HIDDEN_ + idx] = (x[u] - mean) * inv * gamma[idx] + beta[idx];
    }
}

// ---------------------------------------------------------------------------
static const int DSM_GEMM   = 4 * 128 * 36 * 4;   // 73728
static const int DSM_ROWSUM = 2 * 128 * 68 * 4;   // 69632
static const int DSM_FUSED  = 26112 * 4;          // 104448

extern "C" void kernel_launch(void* const* d_in, const int* in_sizes, int n_in,
                              void* d_out, int out_size)
{
    const float* query = (const float*)d_in[0];
    const float* key_  = (const float*)d_in[1];
    const float* value = (const float*)d_in[2];
    const float* Wq = (const float*)d_in[3];
    const float* bq = (const float*)d_in[4];
    const float* Wk = (const float*)d_in[5];
    const float* bk = (const float*)d_in[6];
    const float* Wv = (const float*)d_in[7];
    const float* bv = (const float*)d_in[8];
    const float* Wo = (const float*)d_in[9];
    const float* bo = (const float*)d_in[10];
    const float* gamma = (const float*)d_in[11];
    const float* beta  = (const float*)d_in[12];
    const float* temp  = (const float*)d_in[13];

    cudaFuncSetAttribute(tc_gemm<true,  true, true >, cudaFuncAttributeMaxDynamicSharedMemorySize, DSM_GEMM);
    cudaFuncSetAttribute(tc_gemm<false, true, false>, cudaFuncAttributeMaxDynamicSharedMemorySize, DSM_GEMM);
    cudaFuncSetAttribute(rowsum_kernel,     cudaFuncAttributeMaxDynamicSharedMemorySize, DSM_ROWSUM);
    cudaFuncSetAttribute(fused_pctx_kernel, cudaFuncAttributeMaxDynamicSharedMemorySize, DSM_FUSED);

    float* out_ln = (float*)d_out;
    float *pQ, *pK, *pV, *pVT, *pCtx, *pO, *pPS, *pP;
    cudaGetSymbolAddress((void**)&pQ,   g_Q);
    cudaGetSymbolAddress((void**)&pK,   g_K);
    cudaGetSymbolAddress((void**)&pV,   g_V);
    cudaGetSymbolAddress((void**)&pVT,  g_VT);
    cudaGetSymbolAddress((void**)&pCtx, g_ctx);
    cudaGetSymbolAddress((void**)&pO,   g_o);
    cudaGetSymbolAddress((void**)&pPS,  g_PS);
    if ((long long)out_size >= LN_N + ATT_N) {
        pP = out_ln + LN_N;           // attn_weights are part of the output
    } else {
        cudaGetSymbolAddress((void**)&pP, g_Pfb);
    }

    // --- Projections: X @ W^T + b (in-frag RNA on A,B; outputs RNA-rounded)
    {
        dim3 g(HIDDEN_ / 128, MTOT_ / 128, 1);
        tc_gemm<true, true, true><<<g, 256, DSM_GEMM>>>(query, Wq, bq, pQ,
            HIDDEN_, HIDDEN_, HIDDEN_, HIDDEN_);
        tc_gemm<true, true, true><<<g, 256, DSM_GEMM>>>(key_,  Wk, bk, pK,
            HIDDEN_, HIDDEN_, HIDDEN_, HIDDEN_);
        tc_gemm<true, true, true><<<g, 256, DSM_GEMM>>>(value, Wv, bv, pV,
            HIDDEN_, HIDDEN_, HIDDEN_, HIDDEN_);
    }

    // --- VT: per-head transpose of V
    {
        dim3 g(SEQ_ / 32, HDIM_ / 32, BATCH_ * HEADS_);
        transpose_v_kernel<<<g, 256>>>(pV, pVT);
    }

    // --- Row sums of exp(S*temp) (no tensor write)
    {
        dim3 g(SEQ_ / 128, SEQ_ / 128, BATCH_ * HEADS_);
        rowsum_kernel<<<g, 256, DSM_ROWSUM>>>(pQ, pK, pPS, temp);
    }

    // --- Fused: invl + single P write + ctx mma
    {
        dim3 g(SEQ_ / 128, BATCH_ * HEADS_, 1);
        fused_pctx_kernel<<<g, 256, DSM_FUSED>>>(pQ, pK, pVT, pPS, pP, pCtx, temp);
    }

    // --- Output projection: o = ctx @ Wo^T + bo
    {
        dim3 g(HIDDEN_ / 128, MTOT_ / 128, 1);
        tc_gemm<false, true, false><<<g, 256, DSM_GEMM>>>(pCtx, Wo, bo, pO,
            HIDDEN_, HIDDEN_, HIDDEN_, HIDDEN_);
    }

    // --- Residual + LayerNorm
    ln_kernel<<<(unsigned)MTOT_, 256>>>(pO, query, gamma, beta, out_ln);
}

// round 9
// speedup vs baseline: 1.0862x; 1.0862x over previous
#include <cuda_runtime.h>
#include <cuda_fp16.h>
#include <math.h>
#include <stdint.h>

// ---------------------------------------------------------------------------
// CrossModalAttention on sm_103 — tf32 mma.sync pipeline (R5 structure),
// E intermediate stored as fp16 (halves E-tensor traffic), QKV merged launch.
//   qkv projections   : ONE launch (grid.z=3), tf32 HMMA, in-frag RNA, bias
//   VT transpose      : per-head V^T (k-contiguous) for ctx mma
//   scores_exp        : E = fp16(exp((Q K^T)*temp)) -> gmem; row partials PS
//   inv_reduce        : invl = 1/sum(PS)
//   ctx_fused         : stream fp16 E, P = E*invl -> gmem fp32 (attn output),
//                       rna(P) -> SMEM, ctx += P @ VT^T
//   out projection    : tf32 HMMA GEMM + bias
//   residual + LayerNorm (fp32)
// Shapes fixed: B=2, S=2048, HIDDEN=1024, HEADS=16, HDIM=64.
// ---------------------------------------------------------------------------

#define HIDDEN_ 1024
#define HEADS_  16
#define HDIM_   64
#define BATCH_  2
#define SEQ_    2048
#define MTOT_   (BATCH_*SEQ_)            // 4096
#define NROWS_  (BATCH_*HEADS_*SEQ_)     // 65536 attention rows

static const long long LN_N  = (long long)MTOT_ * HIDDEN_;               // 4,194,304
static const long long ATT_N = (long long)BATCH_ * HEADS_ * SEQ_ * SEQ_; // 134,217,728

// Scratch (__device__ globals: allocation-free rule)
__device__ float  g_Q  [(size_t)MTOT_ * HIDDEN_];
__device__ float  g_K  [(size_t)MTOT_ * HIDDEN_];
__device__ float  g_V  [(size_t)MTOT_ * HIDDEN_];
__device__ float  g_VT [(size_t)BATCH_ * HEADS_ * HDIM_ * SEQ_];
__device__ float  g_ctx[(size_t)MTOT_ * HIDDEN_];
__device__ float  g_o  [(size_t)MTOT_ * HIDDEN_];
__device__ __half g_E  [(size_t)BATCH_ * HEADS_ * SEQ_ * SEQ_];  // fp16 exp(s*t)
__device__ float  g_PS [(size_t)NROWS_ * 16];                    // partial sums
__device__ float  g_INV[(size_t)NROWS_];                         // 1/l
__device__ float  g_Pfb[(size_t)BATCH_ * HEADS_ * SEQ_ * SEQ_];  // P fallback

// ---------------------------------------------------------------------------
// PTX helpers (sm_80+ portable)
// ---------------------------------------------------------------------------
__device__ __forceinline__ uint32_t smem_u32(const void* p) {
    return (uint32_t)__cvta_generic_to_shared(p);
}
__device__ __forceinline__ float rna_tf32(float x) {
    uint32_t y;
    asm("cvt.rna.tf32.f32 %0, %1;" : "=r"(y) : "f"(x));
    return __uint_as_float(y);
}
__device__ __forceinline__ void cp_async16(uint32_t dst, const void* src) {
    asm volatile("cp.async.cg.shared.global [%0], [%1], 16;" :: "r"(dst), "l"(src));
}
__device__ __forceinline__ void cp_commit() { asm volatile("cp.async.commit_group;" ::: "memory"); }
template <int N>
__device__ __forceinline__ void cp_wait_group() {
    asm volatile("cp.async.wait_group %0;" :: "n"(N) : "memory");
}
__device__ __forceinline__ void st_cs_b32(__half* p, uint32_t v) {
    asm volatile("st.global.cs.b32 [%0], %1;" :: "l"(p), "r"(v) : "memory");
}
__device__ __forceinline__ void st_cs_v4(float* p, float4 v) {
    asm volatile("st.global.cs.v4.f32 [%0], {%1,%2,%3,%4};"
                 :: "l"(p), "f"(v.x), "f"(v.y), "f"(v.z), "f"(v.w) : "memory");
}
__device__ __forceinline__ uint4 ld_cs_v4u(const void* p) {
    uint4 v;
    asm volatile("ld.global.cs.v4.u32 {%0,%1,%2,%3}, [%4];"
                 : "=r"(v.x), "=r"(v.y), "=r"(v.z), "=r"(v.w) : "l"(p));
    return v;
}
// D += A*B, m16n8k8 tf32 (HMMA on tensor pipe)
__device__ __forceinline__ void mma1688(float* d, const uint32_t* a, const uint32_t* b) {
    asm volatile(
        "mma.sync.aligned.m16n8k8.row.col.f32.tf32.tf32.f32 "
        "{%0,%1,%2,%3}, {%4,%5,%6,%7}, {%8,%9}, {%0,%1,%2,%3};"
        : "+f"(d[0]), "+f"(d[1]), "+f"(d[2]), "+f"(d[3])
        : "r"(a[0]), "r"(a[1]), "r"(a[2]), "r"(a[3]), "r"(b[0]), "r"(b[1]));
}

// ---------------------------------------------------------------------------
// GEMM body:  C[m,n] = sum_k A[m,k]*B[n,k] (+bias[n])
// BM=128, BN=128, BK=32 floats. 256 threads = 8 warps (2x4).
// ---------------------------------------------------------------------------
template <bool RA, bool RB, bool ROUND>
__device__ __forceinline__ void gemm_body(
    const float* __restrict__ A, const float* __restrict__ Bm,
    const float* __restrict__ bias, float* __restrict__ C,
    int K, int lda, int ldb, int ldc, int bx, int by)
{
    constexpr int LDS_ = 36;
    constexpr int AS_STAGE = 128 * LDS_;
    constexpr int BS_STAGE = 128 * LDS_;

    extern __shared__ float sm[];
    float* As = sm;
    float* Bs = sm + 2 * AS_STAGE;

    const int tid  = threadIdx.x;
    const int warp = tid >> 5;
    const int lane = tid & 31;
    const int wr = warp & 1, wc = warp >> 1;
    const int g = lane >> 2, t = lane & 3;
    const int row0 = by * 128;
    const int col0 = bx * 128;

    float acc[4][4][4];
#pragma unroll
    for (int i = 0; i < 4; ++i)
#pragma unroll
        for (int j = 0; j < 4; ++j)
#pragma unroll
            for (int q = 0; q < 4; ++q) acc[i][j][q] = 0.0f;

    auto load_tile = [&](int kt) {
        const int st = kt & 1;
        const float* Ag = A + (size_t)row0 * lda + kt * 32;
        float* Ad = As + st * AS_STAGE;
#pragma unroll
        for (int i = 0; i < 4; ++i) {
            int id = tid + i * 256;
            int r = id >> 3, c = id & 7;
            cp_async16(smem_u32(Ad + r * LDS_ + c * 4), Ag + (size_t)r * lda + c * 4);
        }
        const float* Bg = Bm + (size_t)col0 * ldb + kt * 32;
        float* Bd = Bs + st * BS_STAGE;
#pragma unroll
        for (int i = 0; i < 4; ++i) {
            int id = tid + i * 256;
            int r = id >> 3, c = id & 7;
            cp_async16(smem_u32(Bd + r * LDS_ + c * 4), Bg + (size_t)r * ldb + c * 4);
        }
        cp_commit();
    };

    const int T = K >> 5;
    load_tile(0);
    for (int kt = 0; kt < T; ++kt) {
        if (kt + 1 < T) { load_tile(kt + 1); cp_wait_group<1>(); }
        else            { cp_wait_group<0>(); }
        __syncthreads();

        const float* Ab = As + (kt & 1) * AS_STAGE + (wr * 64) * LDS_;
        const float* Bb = Bs + (kt & 1) * BS_STAGE + (wc * 32) * LDS_;
#pragma unroll
        for (int s = 0; s < 4; ++s) {
            const int k0 = s * 8;
            uint32_t a[4][4], b[4][2];
#pragma unroll
            for (int i = 0; i < 4; ++i) {
                const float* ap = Ab + (i * 16 + g) * LDS_ + k0 + t;
                float a0 = ap[0], a1 = ap[8 * LDS_], a2 = ap[4], a3 = ap[8 * LDS_ + 4];
                if (RA) { a0 = rna_tf32(a0); a1 = rna_tf32(a1); a2 = rna_tf32(a2); a3 = rna_tf32(a3); }
                a[i][0] = __float_as_uint(a0);
                a[i][1] = __float_as_uint(a1);
                a[i][2] = __float_as_uint(a2);
                a[i][3] = __float_as_uint(a3);
            }
#pragma unroll
            for (int j = 0; j < 4; ++j) {
                const float* bp = Bb + (j * 8 + g) * LDS_ + k0 + t;
                float b0 = bp[0], b1 = bp[4];
                if (RB) { b0 = rna_tf32(b0); b1 = rna_tf32(b1); }
                b[j][0] = __float_as_uint(b0);
                b[j][1] = __float_as_uint(b1);
            }
#pragma unroll
            for (int i = 0; i < 4; ++i)
#pragma unroll
                for (int j = 0; j < 4; ++j)
                    mma1688(acc[i][j], a[i], b[j]);
        }
        __syncthreads();
    }

#pragma unroll
    for (int i = 0; i < 4; ++i) {
#pragma unroll
        for (int j = 0; j < 4; ++j) {
            const int r = row0 + wr * 64 + i * 16 + g;
            const int c = col0 + wc * 32 + j * 8 + 2 * t;
            float2 v0 = make_float2(acc[i][j][0], acc[i][j][1]);
            float2 v1 = make_float2(acc[i][j][2], acc[i][j][3]);
            if (bias) {
                const float bx_ = bias[c], by_ = bias[c + 1];
                v0.x += bx_; v0.y += by_;
                v1.x += bx_; v1.y += by_;
            }
            if (ROUND) {
                v0.x = rna_tf32(v0.x); v0.y = rna_tf32(v0.y);
                v1.x = rna_tf32(v1.x); v1.y = rna_tf32(v1.y);
            }
            *(float2*)&C[(size_t)r * ldc + c]       = v0;
            *(float2*)&C[(size_t)(r + 8) * ldc + c] = v1;
        }
    }
}

// Merged Q/K/V projections: grid.z selects (X, W, bias, out).
struct QKVPtrs {
    const float* A[3];
    const float* W[3];
    const float* bias[3];
    float*       C[3];
};
__global__ void __launch_bounds__(256)
tc_gemm_qkv(QKVPtrs p)
{
    const int z = blockIdx.z;
    gemm_body<true, true, true>(p.A[z], p.W[z], p.bias[z], p.C[z],
                                HIDDEN_, HIDDEN_, HIDDEN_, HIDDEN_,
                                blockIdx.x, blockIdx.y);
}

// Single GEMM (out projection)
__global__ void __launch_bounds__(256)
tc_gemm_o(const float* __restrict__ A, const float* __restrict__ Bm,
          const float* __restrict__ bias, float* __restrict__ C)
{
    gemm_body<false, true, false>(A, Bm, bias, C,
                                  HIDDEN_, HIDDEN_, HIDDEN_, HIDDEN_,
                                  blockIdx.x, blockIdx.y);
}

// ---------------------------------------------------------------------------
// Per-head V transpose: VT[bh][d][k] = V[b*SEQ+k][h*HDIM+d]
// ---------------------------------------------------------------------------
__global__ void __launch_bounds__(256)
transpose_v_kernel(const float* __restrict__ V, float* __restrict__ VT)
{
    __shared__ float t[32][33];
    const int bh = blockIdx.z;
    const int b = bh / HEADS_, h = bh % HEADS_;
    const int k0 = blockIdx.x * 32;
    const int d0 = blockIdx.y * 32;
    const int tx = threadIdx.x & 31;
    const int ty = threadIdx.x >> 5;
    const float* src = V + (size_t)(b * SEQ_) * HIDDEN_ + h * HDIM_;
#pragma unroll
    for (int j = 0; j < 4; ++j)
        t[ty + 8 * j][tx] = src[(size_t)(k0 + ty + 8 * j) * HIDDEN_ + d0 + tx];
    __syncthreads();
    float* dst = VT + (size_t)bh * HDIM_ * SEQ_;
#pragma unroll
    for (int j = 0; j < 4; ++j)
        dst[(size_t)(d0 + ty + 8 * j) * SEQ_ + k0 + tx] = t[tx][ty + 8 * j];
}

// ---------------------------------------------------------------------------
// Scores + exp: per CTA = 128x128 tile of one (bh). K = 64 (single stage).
// E[tile] = fp16(exp(S*temp)) streamed out; per-row sums -> PS[row][bx].
// ---------------------------------------------------------------------------
__global__ void __launch_bounds__(256)
scores_exp_kernel(const float* __restrict__ Q, const float* __restrict__ K,
                  __half* __restrict__ E, float* __restrict__ PS,
                  const float* __restrict__ tptr)
{
    constexpr int LDP = 68;
    extern __shared__ float sm[];
    float* Qs = sm;                 // 128*68
    float* Ks = sm + 128 * LDP;     // 128*68
    __shared__ float red[512];

    const int bx = blockIdx.x;      // key block (0..15)
    const int by = blockIdx.y;      // query block (0..15)
    const int bh = blockIdx.z;
    const int b = bh >> 4, h = bh & 15;
    const int tid = threadIdx.x, lane = tid & 31, warp = tid >> 5;
    const int wr = warp & 1, wc = warp >> 1;
    const int g = lane >> 2, t = lane & 3;
    const float temp = *tptr;

    const float* Qg = Q + ((size_t)(b * SEQ_) + by * 128) * HIDDEN_ + h * HDIM_;
    const float* Kg = K + ((size_t)(b * SEQ_) + bx * 128) * HIDDEN_ + h * HDIM_;
    __half* Eg = E + ((size_t)bh * SEQ_ + by * 128) * SEQ_ + bx * 128;

#pragma unroll
    for (int i = 0; i < 8; ++i) {
        int id = tid + i * 256;
        int r = id >> 4, c = id & 15;
        cp_async16(smem_u32(Qs + r * LDP + c * 4), Qg + (size_t)r * HIDDEN_ + c * 4);
    }
#pragma unroll
    for (int i = 0; i < 8; ++i) {
        int id = tid + i * 256;
        int r = id >> 4, c = id & 15;
        cp_async16(smem_u32(Ks + r * LDP + c * 4), Kg + (size_t)r * HIDDEN_ + c * 4);
    }
    cp_commit();
    cp_wait_group<0>();
    __syncthreads();

    float acc[4][4][4];
#pragma unroll
    for (int i = 0; i < 4; ++i)
#pragma unroll
        for (int j = 0; j < 4; ++j)
#pragma unroll
            for (int q = 0; q < 4; ++q) acc[i][j][q] = 0.0f;

#pragma unroll
    for (int s = 0; s < 8; ++s) {
        const int k0 = s * 8;
        uint32_t a[4][4], bf[4][2];
#pragma unroll
        for (int i = 0; i < 4; ++i) {
            const float* ap = Qs + (wr * 64 + i * 16 + g) * LDP + k0 + t;
            a[i][0] = __float_as_uint(ap[0]);
            a[i][1] = __float_as_uint(ap[8 * LDP]);
            a[i][2] = __float_as_uint(ap[4]);
            a[i][3] = __float_as_uint(ap[8 * LDP + 4]);
        }
#pragma unroll
        for (int j = 0; j < 4; ++j) {
            const float* bp = Ks + (wc * 32 + j * 8 + g) * LDP + k0 + t;
            bf[j][0] = __float_as_uint(bp[0]);
            bf[j][1] = __float_as_uint(bp[4]);
        }
#pragma unroll
        for (int i = 0; i < 4; ++i)
#pragma unroll
            for (int j = 0; j < 4; ++j)
                mma1688(acc[i][j], a[i], bf[j]);
    }

    // exp + fp16 store + per-row sums (sums from fp32 values)
    float rs0[4], rs1[4];
#pragma unroll
    for (int i = 0; i < 4; ++i) { rs0[i] = 0.f; rs1[i] = 0.f; }
#pragma unroll
    for (int i = 0; i < 4; ++i) {
        const int rA = wr * 64 + i * 16 + g;
#pragma unroll
        for (int j = 0; j < 4; ++j) {
            const int c = wc * 32 + j * 8 + 2 * t;
            float e0 = __expf(acc[i][j][0] * temp);
            float e1 = __expf(acc[i][j][1] * temp);
            float e2 = __expf(acc[i][j][2] * temp);
            float e3 = __expf(acc[i][j][3] * temp);
            __half2 h01 = __floats2half2_rn(e0, e1);
            __half2 h23 = __floats2half2_rn(e2, e3);
            st_cs_b32(Eg + (size_t)rA * SEQ_ + c, *(uint32_t*)&h01);
            st_cs_b32(Eg + (size_t)(rA + 8) * SEQ_ + c, *(uint32_t*)&h23);
            rs0[i] += e0 + e1;
            rs1[i] += e2 + e3;
        }
    }
#pragma unroll
    for (int i = 0; i < 4; ++i) {
        rs0[i] += __shfl_xor_sync(0xffffffffu, rs0[i], 1);
        rs0[i] += __shfl_xor_sync(0xffffffffu, rs0[i], 2);
        rs1[i] += __shfl_xor_sync(0xffffffffu, rs1[i], 1);
        rs1[i] += __shfl_xor_sync(0xffffffffu, rs1[i], 2);
    }
    if (t == 0) {
#pragma unroll
        for (int i = 0; i < 4; ++i) {
            red[wc * 128 + wr * 64 + i * 16 + g]     = rs0[i];
            red[wc * 128 + wr * 64 + i * 16 + g + 8] = rs1[i];
        }
    }
    __syncthreads();
    if (tid < 128) {
        float s = red[tid] + red[128 + tid] + red[256 + tid] + red[384 + tid];
        PS[((size_t)bh * SEQ_ + by * 128 + tid) * 16 + bx] = s;
    }
}

// ---------------------------------------------------------------------------
// invl[row] = 1 / sum of 16 partials
// ---------------------------------------------------------------------------
__global__ void __launch_bounds__(256)
inv_reduce_kernel(const float* __restrict__ PS, float* __restrict__ INV)
{
    const int i = blockIdx.x * 256 + threadIdx.x;   // 65536 rows
    const float4* p = (const float4*)(PS + (size_t)i * 16);
    float4 a = p[0], b = p[1], c = p[2], d = p[3];
    float s = (a.x + a.y + a.z + a.w) + (b.x + b.y + b.z + b.w)
            + (c.x + c.y + c.z + c.w) + (d.x + d.y + d.z + d.w);
    INV[i] = 1.0f / s;
}

// ---------------------------------------------------------------------------
// Context fused: per CTA = (bh, 128-row strip). K = 2048, BK=32, BN=64.
// Streams fp16 E, writes P = E*invl (fp32, attn output), rna(P)->SMEM,
// ctx += P @ VT^T. 256 threads = 8 warps (2 row x 4 col; WN=16).
// ---------------------------------------------------------------------------
__global__ void __launch_bounds__(256)
ctx_fused_kernel(const __half* __restrict__ E, const float* __restrict__ INV,
                 const float* __restrict__ VT, float* __restrict__ P,
                 float* __restrict__ CTX)
{
    constexpr int LDS_ = 36;
    constexpr int AS_STAGE = 128 * LDS_;   // 4608
    constexpr int BS_STAGE = 64 * LDS_;    // 2304
    extern __shared__ float sm[];
    float* As = sm;                        // 2 stages
    float* Bs = sm + 2 * AS_STAGE;         // 2 stages
    __shared__ float s_inv[128];

    const int strip = blockIdx.x;
    const int bh = blockIdx.y;
    const int b = bh >> 4, h = bh & 15;
    const int tid = threadIdx.x, lane = tid & 31, warp = tid >> 5;
    const int wr = warp & 1, wc = warp >> 1;
    const int g = lane >> 2, t = lane & 3;

    const __half* Eg = E + ((size_t)bh * SEQ_ + strip * 128) * SEQ_;
    float*        Pg = P + ((size_t)bh * SEQ_ + strip * 128) * SEQ_;
    const float*  Vg = VT + (size_t)bh * HDIM_ * SEQ_;
    float*        Cg = CTX + ((size_t)(b * SEQ_) + strip * 128) * HIDDEN_ + h * HDIM_;

    if (tid < 128) s_inv[tid] = INV[(size_t)bh * SEQ_ + strip * 128 + tid];

    // A tile per kt: 128 rows x 32 cols fp16. Chunks of 8 halves (16B):
    // 512 chunks, 2 per thread: id = tid + i*256, r = id>>2, c8 = id&3.
    uint4 cur[2];
    auto ldgA = [&](int kt, uint4* dst) {
#pragma unroll
        for (int i = 0; i < 2; ++i) {
            int id = tid + i * 256;
            int r = id >> 2, c8 = id & 3;
            dst[i] = ld_cs_v4u(Eg + (size_t)r * SEQ_ + kt * 32 + c8 * 8);
        }
    };
    auto loadB = [&](int kt) {
        float* Bd = Bs + (kt & 1) * BS_STAGE;
#pragma unroll
        for (int i = 0; i < 2; ++i) {
            int id = tid + i * 256;
            int r = id >> 3, c = id & 7;
            cp_async16(smem_u32(Bd + r * LDS_ + c * 4), Vg + (size_t)r * SEQ_ + kt * 32 + c * 4);
        }
        cp_commit();
    };
    auto procA = [&](int kt, uint4* v) {
        float* Ad = As + (kt & 1) * AS_STAGE;
#pragma unroll
        for (int i = 0; i < 2; ++i) {
            int id = tid + i * 256;
            int r = id >> 2, c8 = id & 3;
            const float inv = s_inv[r];
            float2 f0 = __half22float2(*(__half2*)&v[i].x);
            float2 f1 = __half22float2(*(__half2*)&v[i].y);
            float2 f2 = __half22float2(*(__half2*)&v[i].z);
            float2 f3 = __half22float2(*(__half2*)&v[i].w);
            float p0 = f0.x * inv, p1 = f0.y * inv;
            float p2 = f1.x * inv, p3 = f1.y * inv;
            float p4 = f2.x * inv, p5 = f2.y * inv;
            float p6 = f3.x * inv, p7 = f3.y * inv;
            float* pd = Pg + (size_t)r * SEQ_ + kt * 32 + c8 * 8;
            st_cs_v4(pd,     make_float4(p0, p1, p2, p3));
            st_cs_v4(pd + 4, make_float4(p4, p5, p6, p7));
            float* ad = Ad + r * LDS_ + c8 * 8;
            *(float4*)(ad)     = make_float4(rna_tf32(p0), rna_tf32(p1), rna_tf32(p2), rna_tf32(p3));
            *(float4*)(ad + 4) = make_float4(rna_tf32(p4), rna_tf32(p5), rna_tf32(p6), rna_tf32(p7));
        }
    };

    float ctx[4][2][4];
#pragma unroll
    for (int i = 0; i < 4; ++i)
#pragma unroll
        for (int j = 0; j < 2; ++j)
#pragma unroll
            for (int q = 0; q < 4; ++q) ctx[i][j][q] = 0.f;

    ldgA(0, cur);
    loadB(0);
    __syncthreads();             // s_inv visible

    for (int kt = 0; kt < 64; ++kt) {
        procA(kt, cur);          // As[kt&1]: last read by mma kt-2 (sync-protected)
        cp_wait_group<0>();      // B tile kt landed
        __syncthreads();         // STS visible; mma kt-1 done everywhere
        if (kt + 1 < 64) {       // safe to touch (kt+1)&1 buffers now
            ldgA(kt + 1, cur);
            loadB(kt + 1);
        }
        const float* Ab = As + (kt & 1) * AS_STAGE + (wr * 64) * LDS_;
        const float* Bb = Bs + (kt & 1) * BS_STAGE + (wc * 16) * LDS_;
#pragma unroll
        for (int s = 0; s < 4; ++s) {
            const int k0 = s * 8;
            uint32_t a[4][4], bf[2][2];
#pragma unroll
            for (int i = 0; i < 4; ++i) {
                const float* ap = Ab + (i * 16 + g) * LDS_ + k0 + t;
                a[i][0] = __float_as_uint(ap[0]);
                a[i][1] = __float_as_uint(ap[8 * LDS_]);
                a[i][2] = __float_as_uint(ap[4]);
                a[i][3] = __float_as_uint(ap[8 * LDS_ + 4]);
            }
#pragma unroll
            for (int j = 0; j < 2; ++j) {
                const float* bp = Bb + (j * 8 + g) * LDS_ + k0 + t;
                bf[j][0] = __float_as_uint(bp[0]);
                bf[j][1] = __float_as_uint(bp[4]);
            }
#pragma unroll
            for (int i = 0; i < 4; ++i)
#pragma unroll
                for (int j = 0; j < 2; ++j)
                    mma1688(ctx[i][j], a[i], bf[j]);
        }
        __syncthreads();
    }

    // write ctx (RNA: feeds out-projection GEMM)
#pragma unroll
    for (int i = 0; i < 4; ++i) {
        const int rA = wr * 64 + i * 16 + g;
#pragma unroll
        for (int j = 0; j < 2; ++j) {
            const int c = wc * 16 + j * 8 + 2 * t;
            *(float2*)(Cg + (size_t)rA * HIDDEN_ + c) =
                make_float2(rna_tf32(ctx[i][j][0]), rna_tf32(ctx[i][j][1]));
            *(float2*)(Cg + (size_t)(rA + 8) * HIDDEN_ + c) =
                make_float2(rna_tf32(ctx[i][j][2]), rna_tf32(ctx[i][j][3]));
        }
    }
}

// ---------------------------------------------------------------------------
// Residual + LayerNorm (fp32)
// ---------------------------------------------------------------------------
__global__ void __launch_bounds__(256)
ln_kernel(const float* __restrict__ o, const float* __restrict__ resid,
          const float* __restrict__ gamma, const float* __restrict__ beta,
          float* __restrict__ out)
{
    __shared__ float red1[8], red2[8];
    __shared__ float bmean, binv;

    const size_t row = blockIdx.x;
    const int tid = threadIdx.x;
    const int lane = tid & 31, wid = tid >> 5;
    const float* po = o + row * HIDDEN_;
    const float* pr = resid + row * HIDDEN_;

    float x[4];
    float s = 0.0f, s2 = 0.0f;
#pragma unroll
    for (int u = 0; u < 4; ++u) {
        const int idx = tid + 256 * u;
        x[u] = po[idx] + pr[idx];
        s += x[u];
        s2 += x[u] * x[u];
    }
#pragma unroll
    for (int of = 16; of; of >>= 1) {
        s  += __shfl_xor_sync(0xffffffffu, s,  of);
        s2 += __shfl_xor_sync(0xffffffffu, s2, of);
    }
    if (lane == 0) { red1[wid] = s; red2[wid] = s2; }
    __syncthreads();
    if (wid == 0) {
        float t1 = (lane < 8) ? red1[lane] : 0.0f;
        float t2 = (lane < 8) ? red2[lane] : 0.0f;
#pragma unroll
        for (int of = 16; of; of >>= 1) {
            t1 += __shfl_xor_sync(0xffffffffu, t1, of);
            t2 += __shfl_xor_sync(0xffffffffu, t2, of);
        }
        if (lane == 0) {
            const float mean = t1 * (1.0f / HIDDEN_);
            const float var  = t2 * (1.0f / HIDDEN_) - mean * mean;
            bmean = mean;
            binv  = rsqrtf(var + 1e-5f);
        }
    }
    __syncthreads();
    const float mean = bmean, inv = binv;
#pragma unroll
    for (int u = 0; u < 4; ++u) {
        const int idx = tid + 256 * u;
        out[row * HIDDEN_ + idx] = (x[u] - mean) * inv * gamma[idx] + beta[idx];
    }
}

// ---------------------------------------------------------------------------
static const int DSM_GEMM   = 4 * 128 * 36 * 4;                 // 73728
static const int DSM_SCORES = 2 * 128 * 68 * 4;                 // 69632
static const int DSM_CTX    = (2 * 128 * 36 + 2 * 64 * 36) * 4; // 55296

extern "C" void kernel_launch(void* const* d_in, const int* in_sizes, int n_in,
                              void* d_out, int out_size)
{
    const float* query = (const float*)d_in[0];
    const float* key_  = (const float*)d_in[1];
    const float* value = (const float*)d_in[2];
    const float* Wq = (const float*)d_in[3];
    const float* bq = (const float*)d_in[4];
    const float* Wk = (const float*)d_in[5];
    const float* bk = (const float*)d_in[6];
    const float* Wv = (const float*)d_in[7];
    const float* bv = (const float*)d_in[8];
    const float* Wo = (const float*)d_in[9];
    const float* bo = (const float*)d_in[10];
    const float* gamma = (const float*)d_in[11];
    const float* beta  = (const float*)d_in[12];
    const float* temp  = (const float*)d_in[13];

    cudaFuncSetAttribute(tc_gemm_qkv, cudaFuncAttributeMaxDynamicSharedMemorySize, DSM_GEMM);
    cudaFuncSetAttribute(tc_gemm_o,   cudaFuncAttributeMaxDynamicSharedMemorySize, DSM_GEMM);
    cudaFuncSetAttribute(scores_exp_kernel, cudaFuncAttributeMaxDynamicSharedMemorySize, DSM_SCORES);
    cudaFuncSetAttribute(ctx_fused_kernel,  cudaFuncAttributeMaxDynamicSharedMemorySize, DSM_CTX);

    float* out_ln = (float*)d_out;
    float *pQ, *pK, *pV, *pVT, *pCtx, *pO, *pPS, *pINV, *pP;
    __half* pE;
    cudaGetSymbolAddress((void**)&pQ,   g_Q);
    cudaGetSymbolAddress((void**)&pK,   g_K);
    cudaGetSymbolAddress((void**)&pV,   g_V);
    cudaGetSymbolAddress((void**)&pVT,  g_VT);
    cudaGetSymbolAddress((void**)&pCtx, g_ctx);
    cudaGetSymbolAddress((void**)&pO,   g_o);
    cudaGetSymbolAddress((void**)&pE,   g_E);
    cudaGetSymbolAddress((void**)&pPS,  g_PS);
    cudaGetSymbolAddress((void**)&pINV, g_INV);
    if ((long long)out_size >= LN_N + ATT_N) {
        pP = out_ln + LN_N;           // attn_weights are part of the output
    } else {
        cudaGetSymbolAddress((void**)&pP, g_Pfb);
    }

    // --- Merged Q/K/V projections (one launch, grid.z = 3)
    {
        QKVPtrs p;
        p.A[0] = query; p.A[1] = key_; p.A[2] = value;
        p.W[0] = Wq;    p.W[1] = Wk;   p.W[2] = Wv;
        p.bias[0] = bq; p.bias[1] = bk; p.bias[2] = bv;
        p.C[0] = pQ;    p.C[1] = pK;   p.C[2] = pV;
        dim3 g(HIDDEN_ / 128, MTOT_ / 128, 3);
        tc_gemm_qkv<<<g, 256, DSM_GEMM>>>(p);
    }

    // --- VT: per-head transpose of V
    {
        dim3 g(SEQ_ / 32, HDIM_ / 32, BATCH_ * HEADS_);
        transpose_v_kernel<<<g, 256>>>(pV, pVT);
    }

    // --- Scores + exp (fp16 E) + partial sums
    {
        dim3 g(SEQ_ / 128, SEQ_ / 128, BATCH_ * HEADS_);
        scores_exp_kernel<<<g, 256, DSM_SCORES>>>(pQ, pK, pE, pPS, temp);
    }

    // --- invl
    inv_reduce_kernel<<<NROWS_ / 256, 256>>>(pPS, pINV);

    // --- Context fused: P write (fp32) + ctx mma
    {
        dim3 g(SEQ_ / 128, BATCH_ * HEADS_, 1);
        ctx_fused_kernel<<<g, 256, DSM_CTX>>>(pE, pINV, pVT, pP, pCtx);
    }

    // --- Output projection: o = ctx @ Wo^T + bo
    {
        dim3 g(HIDDEN_ / 128, MTOT_ / 128, 1);
        tc_gemm_o<<<g, 256, DSM_GEMM>>>(pCtx, Wo, bo, pO);
    }

    // --- Residual + LayerNorm
    ln_kernel<<<(unsigned)MTOT_, 256>>>(pO, query, gamma, beta, out_ln);
}

// round 10
// speedup vs baseline: 1.3857x; 1.2756x over previous
#include <cuda_runtime.h>
#include <cuda_fp16.h>
#include <math.h>
#include <stdint.h>

// ---------------------------------------------------------------------------
// CrossModalAttention on sm_103 — fp16 mma.sync (m16n8k16, fp32 accum):
//   cvt                : inputs + weights fp32 -> fp16 (one batched launch)
//   qkv projections    : ONE launch (grid.z=3), fp16 HMMA, bias, fp16 out
//   VT transpose       : per-head V^T fp16
//   scores_exp         : E = fp16(exp((Q K^T)*temp)) -> gmem; row partials PS
//   inv_reduce         : invl = 1/sum(PS)
//   ctx_fused          : stream fp16 E, P = E*invl -> gmem fp32 (attn out),
//                        fp16(P) -> SMEM, ctx += P @ VT^T (fp16 mma)
//   out projection     : fp16 HMMA + bias -> fp32 o
//   residual + LayerNorm (fp32)
// Shapes fixed: B=2, S=2048, HIDDEN=1024, HEADS=16, HDIM=64.
// ---------------------------------------------------------------------------

#define HIDDEN_ 1024
#define HEADS_  16
#define HDIM_   64
#define BATCH_  2
#define SEQ_    2048
#define MTOT_   (BATCH_*SEQ_)            // 4096
#define NROWS_  (BATCH_*HEADS_*SEQ_)     // 65536

static const long long LN_N  = (long long)MTOT_ * HIDDEN_;               // 4,194,304
static const long long ATT_N = (long long)BATCH_ * HEADS_ * SEQ_ * SEQ_; // 134,217,728

// Scratch (__device__ globals; 16B-aligned for vector ld/st)
__device__ __align__(16) __half g_q16in[(size_t)MTOT_ * HIDDEN_];
__device__ __align__(16) __half g_k16in[(size_t)MTOT_ * HIDDEN_];
__device__ __align__(16) __half g_v16in[(size_t)MTOT_ * HIDDEN_];
__device__ __align__(16) __half g_W16 [(size_t)4 * HIDDEN_ * HIDDEN_];   // Wq,Wk,Wv,Wo
__device__ __align__(16) __half g_Q16 [(size_t)MTOT_ * HIDDEN_];
__device__ __align__(16) __half g_K16 [(size_t)MTOT_ * HIDDEN_];
__device__ __align__(16) __half g_V16 [(size_t)MTOT_ * HIDDEN_];
__device__ __align__(16) __half g_VT16[(size_t)BATCH_ * HEADS_ * HDIM_ * SEQ_];
__device__ __align__(16) __half g_ctx16[(size_t)MTOT_ * HIDDEN_];
__device__ __align__(16) __half g_E  [(size_t)BATCH_ * HEADS_ * SEQ_ * SEQ_];
__device__ float  g_o  [(size_t)MTOT_ * HIDDEN_];
__device__ float  g_PS [(size_t)NROWS_ * 16];
__device__ float  g_INV[(size_t)NROWS_];
__device__ float  g_Pfb[(size_t)BATCH_ * HEADS_ * SEQ_ * SEQ_];

// ---------------------------------------------------------------------------
// PTX helpers (sm_80+ portable)
// ---------------------------------------------------------------------------
__device__ __forceinline__ uint32_t smem_u32(const void* p) {
    return (uint32_t)__cvta_generic_to_shared(p);
}
__device__ __forceinline__ void cp_async16(uint32_t dst, const void* src) {
    asm volatile("cp.async.cg.shared.global [%0], [%1], 16;" :: "r"(dst), "l"(src));
}
__device__ __forceinline__ void cp_commit() { asm volatile("cp.async.commit_group;" ::: "memory"); }
template <int N>
__device__ __forceinline__ void cp_wait_group() {
    asm volatile("cp.async.wait_group %0;" :: "n"(N) : "memory");
}
__device__ __forceinline__ void st_cs_b32(__half* p, uint32_t v) {
    asm volatile("st.global.cs.b32 [%0], %1;" :: "l"(p), "r"(v) : "memory");
}
__device__ __forceinline__ void st_cs_v4(float* p, float4 v) {
    asm volatile("st.global.cs.v4.f32 [%0], {%1,%2,%3,%4};"
                 :: "l"(p), "f"(v.x), "f"(v.y), "f"(v.z), "f"(v.w) : "memory");
}
__device__ __forceinline__ uint4 ld_cs_v4u(const void* p) {
    uint4 v;
    asm volatile("ld.global.cs.v4.u32 {%0,%1,%2,%3}, [%4];"
                 : "=r"(v.x), "=r"(v.y), "=r"(v.z), "=r"(v.w) : "l"(p));
    return v;
}
// D += A*B, m16n8k16 fp16 inputs, fp32 accumulate
__device__ __forceinline__ void mma16816(float* d, const uint32_t* a, const uint32_t* b) {
    asm volatile(
        "mma.sync.aligned.m16n8k16.row.col.f32.f16.f16.f32 "
        "{%0,%1,%2,%3}, {%4,%5,%6,%7}, {%8,%9}, {%0,%1,%2,%3};"
        : "+f"(d[0]), "+f"(d[1]), "+f"(d[2]), "+f"(d[3])
        : "r"(a[0]), "r"(a[1]), "r"(a[2]), "r"(a[3]), "r"(b[0]), "r"(b[1]));
}

// ---------------------------------------------------------------------------
// Batched fp32 -> fp16 conversion (7 tensors, grid.y selects)
// ---------------------------------------------------------------------------
struct Cvt7 {
    const float* src[7];
    __half*      dst[7];
    int          n8[7];
};
__global__ void __launch_bounds__(256)
cvt_kernel(Cvt7 c)
{
    const int z = blockIdx.y;
    const int i = blockIdx.x * 256 + threadIdx.x;
    if (i < c.n8[z]) {
        const float4* s = (const float4*)c.src[z] + (size_t)i * 2;
        float4 a = s[0], b = s[1];
        __half2 h0 = __floats2half2_rn(a.x, a.y);
        __half2 h1 = __floats2half2_rn(a.z, a.w);
        __half2 h2 = __floats2half2_rn(b.x, b.y);
        __half2 h3 = __floats2half2_rn(b.z, b.w);
        uint4 o;
        o.x = *(uint32_t*)&h0; o.y = *(uint32_t*)&h1;
        o.z = *(uint32_t*)&h2; o.w = *(uint32_t*)&h3;
        ((uint4*)c.dst[z])[i] = o;
    }
}

// ---------------------------------------------------------------------------
// fp16 GEMM body: C[m,n] = sum_k A[m,k]*B[n,k] + bias[n]
// BM=BN=128, BK=64 halves. 256 threads = 8 warps (2x4). LDH=72 halves.
// ---------------------------------------------------------------------------
template <bool OUT16>
__device__ __forceinline__ void gemm16_body(
    const __half* __restrict__ A, const __half* __restrict__ Bm,
    const float* __restrict__ bias, void* __restrict__ Cv,
    int K, int lda, int ldb, int ldc, int bx, int by)
{
    constexpr int LDH = 72;
    constexpr int STAGE = 128 * LDH;         // halves

    extern __shared__ __half smh[];
    __half* As = smh;                        // 2 stages
    __half* Bs = smh + 2 * STAGE;            // 2 stages

    const int tid  = threadIdx.x;
    const int warp = tid >> 5;
    const int lane = tid & 31;
    const int wr = warp & 1, wc = warp >> 1;
    const int g = lane >> 2, t = lane & 3;
    const int row0 = by * 128;
    const int col0 = bx * 128;

    float acc[4][4][4];
#pragma unroll
    for (int i = 0; i < 4; ++i)
#pragma unroll
        for (int j = 0; j < 4; ++j)
#pragma unroll
            for (int q = 0; q < 4; ++q) acc[i][j][q] = 0.0f;

    auto load_tile = [&](int kt) {
        const int st = kt & 1;
        const __half* Ag = A + (size_t)row0 * lda + kt * 64;
        __half* Ad = As + st * STAGE;
#pragma unroll
        for (int i = 0; i < 4; ++i) {        // 128 rows x 8 chunks(8h)
            int id = tid + i * 256;
            int r = id >> 3, c = id & 7;
            cp_async16(smem_u32(Ad + r * LDH + c * 8), Ag + (size_t)r * lda + c * 8);
        }
        const __half* Bg = Bm + (size_t)col0 * ldb + kt * 64;
        __half* Bd = Bs + st * STAGE;
#pragma unroll
        for (int i = 0; i < 4; ++i) {
            int id = tid + i * 256;
            int r = id >> 3, c = id & 7;
            cp_async16(smem_u32(Bd + r * LDH + c * 8), Bg + (size_t)r * ldb + c * 8);
        }
        cp_commit();
    };

    const int T = K >> 6;                    // 64-halve k-tiles
    load_tile(0);
    for (int kt = 0; kt < T; ++kt) {
        if (kt + 1 < T) { load_tile(kt + 1); cp_wait_group<1>(); }
        else            { cp_wait_group<0>(); }
        __syncthreads();

        const __half* Ab = As + (kt & 1) * STAGE + (wr * 64) * LDH;
        const __half* Bb = Bs + (kt & 1) * STAGE + (wc * 32) * LDH;
#pragma unroll
        for (int s = 0; s < 4; ++s) {
            const int k0 = s * 16;
            uint32_t a[4][4], b[4][2];
#pragma unroll
            for (int i = 0; i < 4; ++i) {
                const __half* ap = Ab + (i * 16 + g) * LDH + k0 + 2 * t;
                a[i][0] = *(const uint32_t*)(ap);
                a[i][1] = *(const uint32_t*)(ap + 8 * LDH);
                a[i][2] = *(const uint32_t*)(ap + 8);
                a[i][3] = *(const uint32_t*)(ap + 8 * LDH + 8);
            }
#pragma unroll
            for (int j = 0; j < 4; ++j) {
                const __half* bp = Bb + (j * 8 + g) * LDH + k0 + 2 * t;
                b[j][0] = *(const uint32_t*)(bp);
                b[j][1] = *(const uint32_t*)(bp + 8);
            }
#pragma unroll
            for (int i = 0; i < 4; ++i)
#pragma unroll
                for (int j = 0; j < 4; ++j)
                    mma16816(acc[i][j], a[i], b[j]);
        }
        __syncthreads();
    }

#pragma unroll
    for (int i = 0; i < 4; ++i) {
#pragma unroll
        for (int j = 0; j < 4; ++j) {
            const int r = row0 + wr * 64 + i * 16 + g;
            const int c = col0 + wc * 32 + j * 8 + 2 * t;
            const float bx_ = bias[c], by_ = bias[c + 1];
            float v00 = acc[i][j][0] + bx_, v01 = acc[i][j][1] + by_;
            float v10 = acc[i][j][2] + bx_, v11 = acc[i][j][3] + by_;
            if (OUT16) {
                __half* C16 = (__half*)Cv;
                __half2 h0 = __floats2half2_rn(v00, v01);
                __half2 h1 = __floats2half2_rn(v10, v11);
                *(__half2*)(C16 + (size_t)r * ldc + c)       = h0;
                *(__half2*)(C16 + (size_t)(r + 8) * ldc + c) = h1;
            } else {
                float* C32 = (float*)Cv;
                *(float2*)(C32 + (size_t)r * ldc + c)       = make_float2(v00, v01);
                *(float2*)(C32 + (size_t)(r + 8) * ldc + c) = make_float2(v10, v11);
            }
        }
    }
}

// Merged Q/K/V projections (fp16 in/out)
struct QKV16 {
    const __half* A[3];
    const __half* W[3];
    const float*  bias[3];
    __half*       C[3];
};
__global__ void __launch_bounds__(256)
gemm16_qkv(QKV16 p)
{
    const int z = blockIdx.z;
    gemm16_body<true>(p.A[z], p.W[z], p.bias[z], p.C[z],
                      HIDDEN_, HIDDEN_, HIDDEN_, HIDDEN_, blockIdx.x, blockIdx.y);
}
// Out projection (fp16 in, fp32 out)
__global__ void __launch_bounds__(256)
gemm16_o(const __half* __restrict__ A, const __half* __restrict__ Bm,
         const float* __restrict__ bias, float* __restrict__ C)
{
    gemm16_body<false>(A, Bm, bias, C, HIDDEN_, HIDDEN_, HIDDEN_, HIDDEN_,
                       blockIdx.x, blockIdx.y);
}

// ---------------------------------------------------------------------------
// Per-head V transpose (fp16): VT[bh][d][k] = V[b*SEQ+k][h*HDIM+d]
// ---------------------------------------------------------------------------
__global__ void __launch_bounds__(256)
transpose_v_kernel(const __half* __restrict__ V, __half* __restrict__ VT)
{
    __shared__ __half t[32][34];
    const int bh = blockIdx.z;
    const int b = bh / HEADS_, h = bh % HEADS_;
    const int k0 = blockIdx.x * 32;
    const int d0 = blockIdx.y * 32;
    const int tx = threadIdx.x & 31;
    const int ty = threadIdx.x >> 5;
    const __half* src = V + (size_t)(b * SEQ_) * HIDDEN_ + h * HDIM_;
#pragma unroll
    for (int j = 0; j < 4; ++j)
        t[ty + 8 * j][tx] = src[(size_t)(k0 + ty + 8 * j) * HIDDEN_ + d0 + tx];
    __syncthreads();
    __half* dst = VT + (size_t)bh * HDIM_ * SEQ_;
#pragma unroll
    for (int j = 0; j < 4; ++j)
        dst[(size_t)(d0 + ty + 8 * j) * SEQ_ + k0 + tx] = t[tx][ty + 8 * j];
}

// ---------------------------------------------------------------------------
// Scores + exp (fp16 mma): per CTA = 128x128 S tile. d=64 single stage.
// E = fp16(exp(S*temp)); per-row partials -> PS[row][bx]. LDH=72.
// ---------------------------------------------------------------------------
__global__ void __launch_bounds__(256)
scores_exp_kernel(const __half* __restrict__ Q, const __half* __restrict__ K,
                  __half* __restrict__ E, float* __restrict__ PS,
                  const float* __restrict__ tptr)
{
    constexpr int LDH = 72;
    extern __shared__ __half smh[];
    __half* Qs = smh;                  // 128*72
    __half* Ks = smh + 128 * LDH;      // 128*72
    __shared__ float red[512];

    const int bx = blockIdx.x;
    const int by = blockIdx.y;
    const int bh = blockIdx.z;
    const int b = bh >> 4, h = bh & 15;
    const int tid = threadIdx.x, lane = tid & 31, warp = tid >> 5;
    const int wr = warp & 1, wc = warp >> 1;
    const int g = lane >> 2, t = lane & 3;
    const float temp = *tptr;

    const __half* Qg = Q + ((size_t)(b * SEQ_) + by * 128) * HIDDEN_ + h * HDIM_;
    const __half* Kg = K + ((size_t)(b * SEQ_) + bx * 128) * HIDDEN_ + h * HDIM_;
    __half* Eg = E + ((size_t)bh * SEQ_ + by * 128) * SEQ_ + bx * 128;

#pragma unroll
    for (int i = 0; i < 4; ++i) {      // 128 rows x 8 chunks(8h) = 1024
        int id = tid + i * 256;
        int r = id >> 3, c = id & 7;
        cp_async16(smem_u32(Qs + r * LDH + c * 8), Qg + (size_t)r * HIDDEN_ + c * 8);
    }
#pragma unroll
    for (int i = 0; i < 4; ++i) {
        int id = tid + i * 256;
        int r = id >> 3, c = id & 7;
        cp_async16(smem_u32(Ks + r * LDH + c * 8), Kg + (size_t)r * HIDDEN_ + c * 8);
    }
    cp_commit();
    cp_wait_group<0>();
    __syncthreads();

    float acc[4][4][4];
#pragma unroll
    for (int i = 0; i < 4; ++i)
#pragma unroll
        for (int j = 0; j < 4; ++j)
#pragma unroll
            for (int q = 0; q < 4; ++q) acc[i][j][q] = 0.0f;

#pragma unroll
    for (int s = 0; s < 4; ++s) {      // d = 4 x k16
        const int k0 = s * 16;
        uint32_t a[4][4], bf[4][2];
#pragma unroll
        for (int i = 0; i < 4; ++i) {
            const __half* ap = Qs + (wr * 64 + i * 16 + g) * LDH + k0 + 2 * t;
            a[i][0] = *(const uint32_t*)(ap);
            a[i][1] = *(const uint32_t*)(ap + 8 * LDH);
            a[i][2] = *(const uint32_t*)(ap + 8);
            a[i][3] = *(const uint32_t*)(ap + 8 * LDH + 8);
        }
#pragma unroll
        for (int j = 0; j < 4; ++j) {
            const __half* bp = Ks + (wc * 32 + j * 8 + g) * LDH + k0 + 2 * t;
            bf[j][0] = *(const uint32_t*)(bp);
            bf[j][1] = *(const uint32_t*)(bp + 8);
        }
#pragma unroll
        for (int i = 0; i < 4; ++i)
#pragma unroll
            for (int j = 0; j < 4; ++j)
                mma16816(acc[i][j], a[i], bf[j]);
    }

    // exp + fp16 store + per-row sums
    float rs0[4], rs1[4];
#pragma unroll
    for (int i = 0; i < 4; ++i) { rs0[i] = 0.f; rs1[i] = 0.f; }
#pragma unroll
    for (int i = 0; i < 4; ++i) {
        const int rA = wr * 64 + i * 16 + g;
#pragma unroll
        for (int j = 0; j < 4; ++j) {
            const int c = wc * 32 + j * 8 + 2 * t;
            float e0 = __expf(acc[i][j][0] * temp);
            float e1 = __expf(acc[i][j][1] * temp);
            float e2 = __expf(acc[i][j][2] * temp);
            float e3 = __expf(acc[i][j][3] * temp);
            __half2 h01 = __floats2half2_rn(e0, e1);
            __half2 h23 = __floats2half2_rn(e2, e3);
            st_cs_b32(Eg + (size_t)rA * SEQ_ + c, *(uint32_t*)&h01);
            st_cs_b32(Eg + (size_t)(rA + 8) * SEQ_ + c, *(uint32_t*)&h23);
            rs0[i] += e0 + e1;
            rs1[i] += e2 + e3;
        }
    }
#pragma unroll
    for (int i = 0; i < 4; ++i) {
        rs0[i] += __shfl_xor_sync(0xffffffffu, rs0[i], 1);
        rs0[i] += __shfl_xor_sync(0xffffffffu, rs0[i], 2);
        rs1[i] += __shfl_xor_sync(0xffffffffu, rs1[i], 1);
        rs1[i] += __shfl_xor_sync(0xffffffffu, rs1[i], 2);
    }
    if (t == 0) {
#pragma unroll
        for (int i = 0; i < 4; ++i) {
            red[wc * 128 + wr * 64 + i * 16 + g]     = rs0[i];
            red[wc * 128 + wr * 64 + i * 16 + g + 8] = rs1[i];
        }
    }
    __syncthreads();
    if (tid < 128) {
        float s = red[tid] + red[128 + tid] + red[256 + tid] + red[384 + tid];
        PS[((size_t)bh * SEQ_ + by * 128 + tid) * 16 + bx] = s;
    }
}

// ---------------------------------------------------------------------------
// invl[row] = 1 / sum of 16 partials
// ---------------------------------------------------------------------------
__global__ void __launch_bounds__(256)
inv_reduce_kernel(const float* __restrict__ PS, float* __restrict__ INV)
{
    const int i = blockIdx.x * 256 + threadIdx.x;
    const float4* p = (const float4*)(PS + (size_t)i * 16);
    float4 a = p[0], b = p[1], c = p[2], d = p[3];
    float s = (a.x + a.y + a.z + a.w) + (b.x + b.y + b.z + b.w)
            + (c.x + c.y + c.z + c.w) + (d.x + d.y + d.z + d.w);
    INV[i] = 1.0f / s;
}

// ---------------------------------------------------------------------------
// Context fused (fp16 mma): per CTA = (bh, 128-row strip). K=2048, BK=32.
// Stream fp16 E -> P fp32 gmem (attn output) + fp16 Ps SMEM; ctx += P@VT^T.
// LDH=40 halves. 8 warps (2 row x 4 col; WN=16).
// ---------------------------------------------------------------------------
__global__ void __launch_bounds__(256)
ctx_fused_kernel(const __half* __restrict__ E, const float* __restrict__ INV,
                 const __half* __restrict__ VT, float* __restrict__ P,
                 __half* __restrict__ CTX)
{
    constexpr int LDH = 40;
    constexpr int AS_STAGE = 128 * LDH;    // halves
    constexpr int BS_STAGE = 64 * LDH;
    extern __shared__ __half smh[];
    __half* As = smh;                      // 2 stages
    __half* Bs = smh + 2 * AS_STAGE;       // 2 stages
    __shared__ float s_inv[128];

    const int strip = blockIdx.x;
    const int bh = blockIdx.y;
    const int b = bh >> 4, h = bh & 15;
    const int tid = threadIdx.x, lane = tid & 31, warp = tid >> 5;
    const int wr = warp & 1, wc = warp >> 1;
    const int g = lane >> 2, t = lane & 3;

    const __half* Eg = E + ((size_t)bh * SEQ_ + strip * 128) * SEQ_;
    float*        Pg = P + ((size_t)bh * SEQ_ + strip * 128) * SEQ_;
    const __half* Vg = VT + (size_t)bh * HDIM_ * SEQ_;
    __half*       Cg = CTX + ((size_t)(b * SEQ_) + strip * 128) * HIDDEN_ + h * HDIM_;

    if (tid < 128) s_inv[tid] = INV[(size_t)bh * SEQ_ + strip * 128 + tid];

    // A tile per kt: 128 rows x 32 halves = 512 chunks(8h); 2/thread
    uint4 cur[2];
    auto ldgA = [&](int kt, uint4* dst) {
#pragma unroll
        for (int i = 0; i < 2; ++i) {
            int id = tid + i * 256;
            int r = id >> 2, c8 = id & 3;
            dst[i] = ld_cs_v4u(Eg + (size_t)r * SEQ_ + kt * 32 + c8 * 8);
        }
    };
    auto loadB = [&](int kt) {             // 64 d-rows x 32 halves = 256 chunks
        __half* Bd = Bs + (kt & 1) * BS_STAGE;
        int r = tid >> 2, c8 = tid & 3;
        cp_async16(smem_u32(Bd + r * LDH + c8 * 8), Vg + (size_t)r * SEQ_ + kt * 32 + c8 * 8);
        cp_commit();
    };
    auto procA = [&](int kt, uint4* v) {
        __half* Ad = As + (kt & 1) * AS_STAGE;
#pragma unroll
        for (int i = 0; i < 2; ++i) {
            int id = tid + i * 256;
            int r = id >> 2, c8 = id & 3;
            const float inv = s_inv[r];
            float2 f0 = __half22float2(*(__half2*)&v[i].x);
            float2 f1 = __half22float2(*(__half2*)&v[i].y);
            float2 f2 = __half22float2(*(__half2*)&v[i].z);
            float2 f3 = __half22float2(*(__half2*)&v[i].w);
            float p0 = f0.x * inv, p1 = f0.y * inv;
            float p2 = f1.x * inv, p3 = f1.y * inv;
            float p4 = f2.x * inv, p5 = f2.y * inv;
            float p6 = f3.x * inv, p7 = f3.y * inv;
            float* pd = Pg + (size_t)r * SEQ_ + kt * 32 + c8 * 8;
            st_cs_v4(pd,     make_float4(p0, p1, p2, p3));
            st_cs_v4(pd + 4, make_float4(p4, p5, p6, p7));
            __half2 q0 = __floats2half2_rn(p0, p1);
            __half2 q1 = __floats2half2_rn(p2, p3);
            __half2 q2 = __floats2half2_rn(p4, p5);
            __half2 q3 = __floats2half2_rn(p6, p7);
            uint4 o;
            o.x = *(uint32_t*)&q0; o.y = *(uint32_t*)&q1;
            o.z = *(uint32_t*)&q2; o.w = *(uint32_t*)&q3;
            *(uint4*)(Ad + r * LDH + c8 * 8) = o;    // (40r+8c8)*2 B: 16-aligned
        }
    };

    float ctx[4][2][4];
#pragma unroll
    for (int i = 0; i < 4; ++i)
#pragma unroll
        for (int j = 0; j < 2; ++j)
#pragma unroll
            for (int q = 0; q < 4; ++q) ctx[i][j][q] = 0.f;

    ldgA(0, cur);
    loadB(0);
    __syncthreads();               // s_inv visible

    for (int kt = 0; kt < 64; ++kt) {
        procA(kt, cur);
        cp_wait_group<0>();        // B tile kt landed
        __syncthreads();           // STS visible; mma kt-1 done everywhere
        if (kt + 1 < 64) {
            ldgA(kt + 1, cur);
            loadB(kt + 1);
        }
        const __half* Ab = As + (kt & 1) * AS_STAGE + (wr * 64) * LDH;
        const __half* Bb = Bs + (kt & 1) * BS_STAGE + (wc * 16) * LDH;
#pragma unroll
        for (int s = 0; s < 2; ++s) {        // 32 keys = 2 x k16
            const int k0 = s * 16;
            uint32_t a[4][4], bf[2][2];
#pragma unroll
            for (int i = 0; i < 4; ++i) {
                const __half* ap = Ab + (i * 16 + g) * LDH + k0 + 2 * t;
                a[i][0] = *(const uint32_t*)(ap);
                a[i][1] = *(const uint32_t*)(ap + 8 * LDH);
                a[i][2] = *(const uint32_t*)(ap + 8);
                a[i][3] = *(const uint32_t*)(ap + 8 * LDH + 8);
            }
#pragma unroll
            for (int j = 0; j < 2; ++j) {
                const __half* bp = Bb + (j * 8 + g) * LDH + k0 + 2 * t;
                bf[j][0] = *(const uint32_t*)(bp);
                bf[j][1] = *(const uint32_t*)(bp + 8);
            }
#pragma unroll
            for (int i = 0; i < 4; ++i)
#pragma unroll
                for (int j = 0; j < 2; ++j)
                    mma16816(ctx[i][j], a[i], bf[j]);
        }
        __syncthreads();
    }

    // write ctx as fp16 (feeds out-projection)
#pragma unroll
    for (int i = 0; i < 4; ++i) {
        const int rA = wr * 64 + i * 16 + g;
#pragma unroll
        for (int j = 0; j < 2; ++j) {
            const int c = wc * 16 + j * 8 + 2 * t;
            __half2 h0 = __floats2half2_rn(ctx[i][j][0], ctx[i][j][1]);
            __half2 h1 = __floats2half2_rn(ctx[i][j][2], ctx[i][j][3]);
            *(__half2*)(Cg + (size_t)rA * HIDDEN_ + c)       = h0;
            *(__half2*)(Cg + (size_t)(rA + 8) * HIDDEN_ + c) = h1;
        }
    }
}

// ---------------------------------------------------------------------------
// Residual + LayerNorm (fp32)
// ---------------------------------------------------------------------------
__global__ void __launch_bounds__(256)
ln_kernel(const float* __restrict__ o, const float* __restrict__ resid,
          const float* __restrict__ gamma, const float* __restrict__ beta,
          float* __restrict__ out)
{
    __shared__ float red1[8], red2[8];
    __shared__ float bmean, binv;

    const size_t row = blockIdx.x;
    const int tid = threadIdx.x;
    const int lane = tid & 31, wid = tid >> 5;
    const float* po = o + row * HIDDEN_;
    const float* pr = resid + row * HIDDEN_;

    float x[4];
    float s = 0.0f, s2 = 0.0f;
#pragma unroll
    for (int u = 0; u < 4; ++u) {
        const int idx = tid + 256 * u;
        x[u] = po[idx] + pr[idx];
        s += x[u];
        s2 += x[u] * x[u];
    }
#pragma unroll
    for (int of = 16; of; of >>= 1) {
        s  += __shfl_xor_sync(0xffffffffu, s,  of);
        s2 += __shfl_xor_sync(0xffffffffu, s2, of);
    }
    if (lane == 0) { red1[wid] = s; red2[wid] = s2; }
    __syncthreads();
    if (wid == 0) {
        float t1 = (lane < 8) ? red1[lane] : 0.0f;
        float t2 = (lane < 8) ? red2[lane] : 0.0f;
#pragma unroll
        for (int of = 16; of; of >>= 1) {
            t1 += __shfl_xor_sync(0xffffffffu, t1, of);
            t2 += __shfl_xor_sync(0xffffffffu, t2, of);
        }
        if (lane == 0) {
            const float mean = t1 * (1.0f / HIDDEN_);
            const float var  = t2 * (1.0f / HIDDEN_) - mean * mean;
            bmean = mean;
            binv  = rsqrtf(var + 1e-5f);
        }
    }
    __syncthreads();
    const float mean = bmean, inv = binv;
#pragma unroll
    for (int u = 0; u < 4; ++u) {
        const int idx = tid + 256 * u;
        out[row * HIDDEN_ + idx] = (x[u] - mean) * inv * gamma[idx] + beta[idx];
    }
}

// ---------------------------------------------------------------------------
static const int DSM_GEMM16   = 4 * 128 * 72 * 2;              // 73728
static const int DSM_SCORES16 = 2 * 128 * 72 * 2;              // 36864
static const int DSM_CTX16    = (2 * 128 * 40 + 2 * 64 * 40) * 2;  // 30720

extern "C" void kernel_launch(void* const* d_in, const int* in_sizes, int n_in,
                              void* d_out, int out_size)
{
    const float* query = (const float*)d_in[0];
    const float* key_  = (const float*)d_in[1];
    const float* value = (const float*)d_in[2];
    const float* Wq = (const float*)d_in[3];
    const float* bq = (const float*)d_in[4];
    const float* Wk = (const float*)d_in[5];
    const float* bk = (const float*)d_in[6];
    const float* Wv = (const float*)d_in[7];
    const float* bv = (const float*)d_in[8];
    const float* Wo = (const float*)d_in[9];
    const float* bo = (const float*)d_in[10];
    const float* gamma = (const float*)d_in[11];
    const float* beta  = (const float*)d_in[12];
    const float* temp  = (const float*)d_in[13];

    cudaFuncSetAttribute(gemm16_qkv, cudaFuncAttributeMaxDynamicSharedMemorySize, DSM_GEMM16);
    cudaFuncSetAttribute(gemm16_o,   cudaFuncAttributeMaxDynamicSharedMemorySize, DSM_GEMM16);
    cudaFuncSetAttribute(scores_exp_kernel, cudaFuncAttributeMaxDynamicSharedMemorySize, DSM_SCORES16);
    cudaFuncSetAttribute(ctx_fused_kernel,  cudaFuncAttributeMaxDynamicSharedMemorySize, DSM_CTX16);

    float* out_ln = (float*)d_out;
    __half *pQin, *pKin, *pVin, *pW16, *pQ16, *pK16, *pV16, *pVT16, *pCtx16, *pE;
    float *pO, *pPS, *pINV, *pP;
    cudaGetSymbolAddress((void**)&pQin,  g_q16in);
    cudaGetSymbolAddress((void**)&pKin,  g_k16in);
    cudaGetSymbolAddress((void**)&pVin,  g_v16in);
    cudaGetSymbolAddress((void**)&pW16,  g_W16);
    cudaGetSymbolAddress((void**)&pQ16,  g_Q16);
    cudaGetSymbolAddress((void**)&pK16,  g_K16);
    cudaGetSymbolAddress((void**)&pV16,  g_V16);
    cudaGetSymbolAddress((void**)&pVT16, g_VT16);
    cudaGetSymbolAddress((void**)&pCtx16,g_ctx16);
    cudaGetSymbolAddress((void**)&pE,    g_E);
    cudaGetSymbolAddress((void**)&pO,    g_o);
    cudaGetSymbolAddress((void**)&pPS,   g_PS);
    cudaGetSymbolAddress((void**)&pINV,  g_INV);
    if ((long long)out_size >= LN_N + ATT_N) {
        pP = out_ln + LN_N;           // attn_weights are part of the output
    } else {
        cudaGetSymbolAddress((void**)&pP, g_Pfb);
    }
    const int WN = HIDDEN_ * HIDDEN_;   // 1,048,576

    // --- fp32 -> fp16 conversions (one batched launch)
    {
        Cvt7 c;
        c.src[0] = query; c.dst[0] = pQin;          c.n8[0] = (MTOT_ * HIDDEN_) / 8;
        c.src[1] = key_;  c.dst[1] = pKin;          c.n8[1] = (MTOT_ * HIDDEN_) / 8;
        c.src[2] = value; c.dst[2] = pVin;          c.n8[2] = (MTOT_ * HIDDEN_) / 8;
        c.src[3] = Wq;    c.dst[3] = pW16 + 0ll*WN; c.n8[3] = WN / 8;
        c.src[4] = Wk;    c.dst[4] = pW16 + 1ll*WN; c.n8[4] = WN / 8;
        c.src[5] = Wv;    c.dst[5] = pW16 + 2ll*WN; c.n8[5] = WN / 8;
        c.src[6] = Wo;    c.dst[6] = pW16 + 3ll*WN; c.n8[6] = WN / 8;
        dim3 g((MTOT_ * HIDDEN_ / 8 + 255) / 256, 7, 1);
        cvt_kernel<<<g, 256>>>(c);
    }

    // --- Merged Q/K/V projections (fp16)
    {
        QKV16 p;
        p.A[0] = pQin; p.A[1] = pKin; p.A[2] = pVin;
        p.W[0] = pW16; p.W[1] = pW16 + 1ll*WN; p.W[2] = pW16 + 2ll*WN;
        p.bias[0] = bq; p.bias[1] = bk; p.bias[2] = bv;
        p.C[0] = pQ16; p.C[1] = pK16; p.C[2] = pV16;
        dim3 g(HIDDEN_ / 128, MTOT_ / 128, 3);
        gemm16_qkv<<<g, 256, DSM_GEMM16>>>(p);
    }

    // --- VT transpose (fp16)
    {
        dim3 g(SEQ_ / 32, HDIM_ / 32, BATCH_ * HEADS_);
        transpose_v_kernel<<<g, 256>>>(pV16, pVT16);
    }

    // --- Scores + exp (fp16 mma, fp16 E) + partial sums
    {
        dim3 g(SEQ_ / 128, SEQ_ / 128, BATCH_ * HEADS_);
        scores_exp_kernel<<<g, 256, DSM_SCORES16>>>(pQ16, pK16, pE, pPS, temp);
    }

    // --- invl
    inv_reduce_kernel<<<NROWS_ / 256, 256>>>(pPS, pINV);

    // --- Context fused: P write (fp32) + ctx mma (fp16)
    {
        dim3 g(SEQ_ / 128, BATCH_ * HEADS_, 1);
        ctx_fused_kernel<<<g, 256, DSM_CTX16>>>(pE, pINV, pVT16, pP, pCtx16);
    }

    // --- Output projection: o = ctx @ Wo^T + bo (fp32 out)
    {
        dim3 g(HIDDEN_ / 128, MTOT_ / 128, 1);
        gemm16_o<<<g, 256, DSM_GEMM16>>>(pCtx16, pW16 + 3ll*WN, bo, pO);
    }

    // --- Residual + LayerNorm
    ln_kernel<<<(unsigned)MTOT_, 256>>>(pO, query, gamma, beta, out_ln);
}

// round 11
// speedup vs baseline: 1.7258x; 1.2455x over previous
#include <cuda_runtime.h>
#include <cuda_fp16.h>
#include <math.h>
#include <stdint.h>

// ---------------------------------------------------------------------------
// CrossModalAttention on sm_103 — fp16 mma.sync (m16n8k16, fp32 accum):
//   cvt           : inputs + weights fp32 -> fp16 (one batched launch)
//   qkv proj      : ONE launch (grid.z=3), fp16 HMMA, bias, fp16 out
//   VT transpose  : per-head V^T fp16
//   scores_exp    : E = h2exp2((QK^T)*temp*log2e) fp16; SMEM-staged coalesced
//                   v4 stores; row partials PS (from fp16 E values)
//   inv_reduce    : invl = 1/sum(PS)
//   ctx_fused     : stream fp16 E (BK=64), P = E*invl -> fp32 gmem (attn out),
//                   fp16(P) -> SMEM, ctx += P @ VT^T
//   out proj      : fp16 HMMA + bias -> fp32
//   residual + LayerNorm (fp32)
// Shapes fixed: B=2, S=2048, HIDDEN=1024, HEADS=16, HDIM=64.
// ---------------------------------------------------------------------------

#define HIDDEN_ 1024
#define HEADS_  16
#define HDIM_   64
#define BATCH_  2
#define SEQ_    2048
#define MTOT_   (BATCH_*SEQ_)            // 4096
#define NROWS_  (BATCH_*HEADS_*SEQ_)     // 65536

static const long long LN_N  = (long long)MTOT_ * HIDDEN_;               // 4,194,304
static const long long ATT_N = (long long)BATCH_ * HEADS_ * SEQ_ * SEQ_; // 134,217,728

// Scratch (__device__ globals; 16B-aligned for vector ld/st)
__device__ __align__(16) __half g_q16in[(size_t)MTOT_ * HIDDEN_];
__device__ __align__(16) __half g_k16in[(size_t)MTOT_ * HIDDEN_];
__device__ __align__(16) __half g_v16in[(size_t)MTOT_ * HIDDEN_];
__device__ __align__(16) __half g_W16 [(size_t)4 * HIDDEN_ * HIDDEN_];   // Wq,Wk,Wv,Wo
__device__ __align__(16) __half g_Q16 [(size_t)MTOT_ * HIDDEN_];
__device__ __align__(16) __half g_K16 [(size_t)MTOT_ * HIDDEN_];
__device__ __align__(16) __half g_V16 [(size_t)MTOT_ * HIDDEN_];
__device__ __align__(16) __half g_VT16[(size_t)BATCH_ * HEADS_ * HDIM_ * SEQ_];
__device__ __align__(16) __half g_ctx16[(size_t)MTOT_ * HIDDEN_];
__device__ __align__(16) __half g_E  [(size_t)BATCH_ * HEADS_ * SEQ_ * SEQ_];
__device__ float  g_o  [(size_t)MTOT_ * HIDDEN_];
__device__ float  g_PS [(size_t)NROWS_ * 16];
__device__ float  g_INV[(size_t)NROWS_];
__device__ float  g_Pfb[(size_t)BATCH_ * HEADS_ * SEQ_ * SEQ_];

// ---------------------------------------------------------------------------
// PTX helpers (sm_80+ portable)
// ---------------------------------------------------------------------------
__device__ __forceinline__ uint32_t smem_u32(const void* p) {
    return (uint32_t)__cvta_generic_to_shared(p);
}
__device__ __forceinline__ void cp_async16(uint32_t dst, const void* src) {
    asm volatile("cp.async.cg.shared.global [%0], [%1], 16;" :: "r"(dst), "l"(src));
}
__device__ __forceinline__ void cp_commit() { asm volatile("cp.async.commit_group;" ::: "memory"); }
template <int N>
__device__ __forceinline__ void cp_wait_group() {
    asm volatile("cp.async.wait_group %0;" :: "n"(N) : "memory");
}
__device__ __forceinline__ void st_cs_v4f(float* p, float4 v) {
    asm volatile("st.global.cs.v4.f32 [%0], {%1,%2,%3,%4};"
                 :: "l"(p), "f"(v.x), "f"(v.y), "f"(v.z), "f"(v.w) : "memory");
}
__device__ __forceinline__ void st_cs_v4h(__half* p, uint4 v) {
    asm volatile("st.global.cs.v4.u32 [%0], {%1,%2,%3,%4};"
                 :: "l"(p), "r"(v.x), "r"(v.y), "r"(v.z), "r"(v.w) : "memory");
}
__device__ __forceinline__ uint4 ld_cs_v4u(const void* p) {
    uint4 v;
    asm volatile("ld.global.cs.v4.u32 {%0,%1,%2,%3}, [%4];"
                 : "=r"(v.x), "=r"(v.y), "=r"(v.z), "=r"(v.w) : "l"(p));
    return v;
}
// D += A*B, m16n8k16 fp16 inputs, fp32 accumulate
__device__ __forceinline__ void mma16816(float* d, const uint32_t* a, const uint32_t* b) {
    asm volatile(
        "mma.sync.aligned.m16n8k16.row.col.f32.f16.f16.f32 "
        "{%0,%1,%2,%3}, {%4,%5,%6,%7}, {%8,%9}, {%0,%1,%2,%3};"
        : "+f"(d[0]), "+f"(d[1]), "+f"(d[2]), "+f"(d[3])
        : "r"(a[0]), "r"(a[1]), "r"(a[2]), "r"(a[3]), "r"(b[0]), "r"(b[1]));
}

// ---------------------------------------------------------------------------
// Batched fp32 -> fp16 conversion (7 tensors, grid.y selects)
// ---------------------------------------------------------------------------
struct Cvt7 {
    const float* src[7];
    __half*      dst[7];
    int          n8[7];
};
__global__ void __launch_bounds__(256)
cvt_kernel(Cvt7 c)
{
    const int z = blockIdx.y;
    const int i = blockIdx.x * 256 + threadIdx.x;
    if (i < c.n8[z]) {
        const float4* s = (const float4*)c.src[z] + (size_t)i * 2;
        float4 a = s[0], b = s[1];
        __half2 h0 = __floats2half2_rn(a.x, a.y);
        __half2 h1 = __floats2half2_rn(a.z, a.w);
        __half2 h2 = __floats2half2_rn(b.x, b.y);
        __half2 h3 = __floats2half2_rn(b.z, b.w);
        uint4 o;
        o.x = *(uint32_t*)&h0; o.y = *(uint32_t*)&h1;
        o.z = *(uint32_t*)&h2; o.w = *(uint32_t*)&h3;
        ((uint4*)c.dst[z])[i] = o;
    }
}

// ---------------------------------------------------------------------------
// fp16 GEMM body: C[m,n] = sum_k A[m,k]*B[n,k] + bias[n]
// BM=BN=128, BK=64 halves. 256 threads = 8 warps (2x4). LDH=72.
// ---------------------------------------------------------------------------
template <bool OUT16>
__device__ __forceinline__ void gemm16_body(
    const __half* __restrict__ A, const __half* __restrict__ Bm,
    const float* __restrict__ bias, void* __restrict__ Cv,
    int K, int lda, int ldb, int ldc, int bx, int by)
{
    constexpr int LDH = 72;
    constexpr int STAGE = 128 * LDH;

    extern __shared__ __half smh[];
    __half* As = smh;
    __half* Bs = smh + 2 * STAGE;

    const int tid  = threadIdx.x;
    const int warp = tid >> 5;
    const int lane = tid & 31;
    const int wr = warp & 1, wc = warp >> 1;
    const int g = lane >> 2, t = lane & 3;
    const int row0 = by * 128;
    const int col0 = bx * 128;

    float acc[4][4][4];
#pragma unroll
    for (int i = 0; i < 4; ++i)
#pragma unroll
        for (int j = 0; j < 4; ++j)
#pragma unroll
            for (int q = 0; q < 4; ++q) acc[i][j][q] = 0.0f;

    auto load_tile = [&](int kt) {
        const int st = kt & 1;
        const __half* Ag = A + (size_t)row0 * lda + kt * 64;
        __half* Ad = As + st * STAGE;
#pragma unroll
        for (int i = 0; i < 4; ++i) {
            int id = tid + i * 256;
            int r = id >> 3, c = id & 7;
            cp_async16(smem_u32(Ad + r * LDH + c * 8), Ag + (size_t)r * lda + c * 8);
        }
        const __half* Bg = Bm + (size_t)col0 * ldb + kt * 64;
        __half* Bd = Bs + st * STAGE;
#pragma unroll
        for (int i = 0; i < 4; ++i) {
            int id = tid + i * 256;
            int r = id >> 3, c = id & 7;
            cp_async16(smem_u32(Bd + r * LDH + c * 8), Bg + (size_t)r * ldb + c * 8);
        }
        cp_commit();
    };

    const int T = K >> 6;
    load_tile(0);
    for (int kt = 0; kt < T; ++kt) {
        if (kt + 1 < T) { load_tile(kt + 1); cp_wait_group<1>(); }
        else            { cp_wait_group<0>(); }
        __syncthreads();

        const __half* Ab = As + (kt & 1) * STAGE + (wr * 64) * LDH;
        const __half* Bb = Bs + (kt & 1) * STAGE + (wc * 32) * LDH;
#pragma unroll
        for (int s = 0; s < 4; ++s) {
            const int k0 = s * 16;
            uint32_t a[4][4], b[4][2];
#pragma unroll
            for (int i = 0; i < 4; ++i) {
                const __half* ap = Ab + (i * 16 + g) * LDH + k0 + 2 * t;
                a[i][0] = *(const uint32_t*)(ap);
                a[i][1] = *(const uint32_t*)(ap + 8 * LDH);
                a[i][2] = *(const uint32_t*)(ap + 8);
                a[i][3] = *(const uint32_t*)(ap + 8 * LDH + 8);
            }
#pragma unroll
            for (int j = 0; j < 4; ++j) {
                const __half* bp = Bb + (j * 8 + g) * LDH + k0 + 2 * t;
                b[j][0] = *(const uint32_t*)(bp);
                b[j][1] = *(const uint32_t*)(bp + 8);
            }
#pragma unroll
            for (int i = 0; i < 4; ++i)
#pragma unroll
                for (int j = 0; j < 4; ++j)
                    mma16816(acc[i][j], a[i], b[j]);
        }
        __syncthreads();
    }

#pragma unroll
    for (int i = 0; i < 4; ++i) {
#pragma unroll
        for (int j = 0; j < 4; ++j) {
            const int r = row0 + wr * 64 + i * 16 + g;
            const int c = col0 + wc * 32 + j * 8 + 2 * t;
            const float bx_ = bias[c], by_ = bias[c + 1];
            float v00 = acc[i][j][0] + bx_, v01 = acc[i][j][1] + by_;
            float v10 = acc[i][j][2] + bx_, v11 = acc[i][j][3] + by_;
            if (OUT16) {
                __half* C16 = (__half*)Cv;
                __half2 h0 = __floats2half2_rn(v00, v01);
                __half2 h1 = __floats2half2_rn(v10, v11);
                *(__half2*)(C16 + (size_t)r * ldc + c)       = h0;
                *(__half2*)(C16 + (size_t)(r + 8) * ldc + c) = h1;
            } else {
                float* C32 = (float*)Cv;
                *(float2*)(C32 + (size_t)r * ldc + c)       = make_float2(v00, v01);
                *(float2*)(C32 + (size_t)(r + 8) * ldc + c) = make_float2(v10, v11);
            }
        }
    }
}

struct QKV16 {
    const __half* A[3];
    const __half* W[3];
    const float*  bias[3];
    __half*       C[3];
};
__global__ void __launch_bounds__(256)
gemm16_qkv(QKV16 p)
{
    const int z = blockIdx.z;
    gemm16_body<true>(p.A[z], p.W[z], p.bias[z], p.C[z],
                      HIDDEN_, HIDDEN_, HIDDEN_, HIDDEN_, blockIdx.x, blockIdx.y);
}
__global__ void __launch_bounds__(256)
gemm16_o(const __half* __restrict__ A, const __half* __restrict__ Bm,
         const float* __restrict__ bias, float* __restrict__ C)
{
    gemm16_body<false>(A, Bm, bias, C, HIDDEN_, HIDDEN_, HIDDEN_, HIDDEN_,
                       blockIdx.x, blockIdx.y);
}

// ---------------------------------------------------------------------------
// Per-head V transpose (fp16): VT[bh][d][k] = V[b*SEQ+k][h*HDIM+d]
// ---------------------------------------------------------------------------
__global__ void __launch_bounds__(256)
transpose_v_kernel(const __half* __restrict__ V, __half* __restrict__ VT)
{
    __shared__ __half t[32][34];
    const int bh = blockIdx.z;
    const int b = bh / HEADS_, h = bh % HEADS_;
    const int k0 = blockIdx.x * 32;
    const int d0 = blockIdx.y * 32;
    const int tx = threadIdx.x & 31;
    const int ty = threadIdx.x >> 5;
    const __half* src = V + (size_t)(b * SEQ_) * HIDDEN_ + h * HDIM_;
#pragma unroll
    for (int j = 0; j < 4; ++j)
        t[ty + 8 * j][tx] = src[(size_t)(k0 + ty + 8 * j) * HIDDEN_ + d0 + tx];
    __syncthreads();
    __half* dst = VT + (size_t)bh * HDIM_ * SEQ_;
#pragma unroll
    for (int j = 0; j < 4; ++j)
        dst[(size_t)(d0 + ty + 8 * j) * SEQ_ + k0 + tx] = t[tx][ty + 8 * j];
}

// ---------------------------------------------------------------------------
// Scores + exp (fp16 mma): per CTA = 128x128 S tile, d=64 single stage.
// E = h2exp2(S*temp*log2e) fp16, staged in SMEM (stride 136, conflict-free)
// then coalesced v4 stores. Row partials (from fp16 E) -> PS. LDH=72.
// ---------------------------------------------------------------------------
__global__ void __launch_bounds__(256)
scores_exp_kernel(const __half* __restrict__ Q, const __half* __restrict__ K,
                  __half* __restrict__ E, float* __restrict__ PS,
                  const float* __restrict__ tptr)
{
    constexpr int LDH = 72;
    constexpr int LDE = 136;
    extern __shared__ __half smh[];
    __half* Qs = smh;                  // 128*72
    __half* Ks = smh + 128 * LDH;      // 128*72
    __half* Es = smh;                  // reuse after mma: 128*136 <= 2*128*72
    __shared__ float red[512];

    const int bx = blockIdx.x;
    const int by = blockIdx.y;
    const int bh = blockIdx.z;
    const int b = bh >> 4, h = bh & 15;
    const int tid = threadIdx.x, lane = tid & 31, warp = tid >> 5;
    const int wr = warp & 1, wc = warp >> 1;
    const int g = lane >> 2, t = lane & 3;
    const float tl2e = (*tptr) * 1.4426950408889634f;

    const __half* Qg = Q + ((size_t)(b * SEQ_) + by * 128) * HIDDEN_ + h * HDIM_;
    const __half* Kg = K + ((size_t)(b * SEQ_) + bx * 128) * HIDDEN_ + h * HDIM_;
    __half* Eg = E + ((size_t)bh * SEQ_ + by * 128) * SEQ_ + bx * 128;

#pragma unroll
    for (int i = 0; i < 4; ++i) {
        int id = tid + i * 256;
        int r = id >> 3, c = id & 7;
        cp_async16(smem_u32(Qs + r * LDH + c * 8), Qg + (size_t)r * HIDDEN_ + c * 8);
    }
#pragma unroll
    for (int i = 0; i < 4; ++i) {
        int id = tid + i * 256;
        int r = id >> 3, c = id & 7;
        cp_async16(smem_u32(Ks + r * LDH + c * 8), Kg + (size_t)r * HIDDEN_ + c * 8);
    }
    cp_commit();
    cp_wait_group<0>();
    __syncthreads();

    float acc[4][4][4];
#pragma unroll
    for (int i = 0; i < 4; ++i)
#pragma unroll
        for (int j = 0; j < 4; ++j)
#pragma unroll
            for (int q = 0; q < 4; ++q) acc[i][j][q] = 0.0f;

#pragma unroll
    for (int s = 0; s < 4; ++s) {
        const int k0 = s * 16;
        uint32_t a[4][4], bf[4][2];
#pragma unroll
        for (int i = 0; i < 4; ++i) {
            const __half* ap = Qs + (wr * 64 + i * 16 + g) * LDH + k0 + 2 * t;
            a[i][0] = *(const uint32_t*)(ap);
            a[i][1] = *(const uint32_t*)(ap + 8 * LDH);
            a[i][2] = *(const uint32_t*)(ap + 8);
            a[i][3] = *(const uint32_t*)(ap + 8 * LDH + 8);
        }
#pragma unroll
        for (int j = 0; j < 4; ++j) {
            const __half* bp = Ks + (wc * 32 + j * 8 + g) * LDH + k0 + 2 * t;
            bf[j][0] = *(const uint32_t*)(bp);
            bf[j][1] = *(const uint32_t*)(bp + 8);
        }
#pragma unroll
        for (int i = 0; i < 4; ++i)
#pragma unroll
            for (int j = 0; j < 4; ++j)
                mma16816(acc[i][j], a[i], bf[j]);
    }
    __syncthreads();                   // Qs/Ks reads complete -> reuse as Es

    // E = 2^(s*temp*log2e) via h2exp2; stage in Es; sums from fp16 values
    float rs0[4], rs1[4];
#pragma unroll
    for (int i = 0; i < 4; ++i) { rs0[i] = 0.f; rs1[i] = 0.f; }
#pragma unroll
    for (int i = 0; i < 4; ++i) {
        const int rA = wr * 64 + i * 16 + g;
#pragma unroll
        for (int j = 0; j < 4; ++j) {
            const int c = wc * 32 + j * 8 + 2 * t;
            __half2 e01 = h2exp2(__floats2half2_rn(acc[i][j][0] * tl2e, acc[i][j][1] * tl2e));
            __half2 e23 = h2exp2(__floats2half2_rn(acc[i][j][2] * tl2e, acc[i][j][3] * tl2e));
            *(__half2*)(Es + rA * LDE + c)       = e01;
            *(__half2*)(Es + (rA + 8) * LDE + c) = e23;
            float2 f0 = __half22float2(e01);
            float2 f1 = __half22float2(e23);
            rs0[i] += f0.x + f0.y;
            rs1[i] += f1.x + f1.y;
        }
    }
    __syncthreads();

    // coalesced v4 stores: 128 rows x 128 halves
#pragma unroll
    for (int p = 0; p < 8; ++p) {
        int id = tid + p * 256;
        int r = id >> 4, cc = id & 15;
        uint4 v = *(const uint4*)(Es + r * LDE + cc * 8);
        st_cs_v4h(Eg + (size_t)r * SEQ_ + cc * 8, v);
    }

    // row-sum reduction
#pragma unroll
    for (int i = 0; i < 4; ++i) {
        rs0[i] += __shfl_xor_sync(0xffffffffu, rs0[i], 1);
        rs0[i] += __shfl_xor_sync(0xffffffffu, rs0[i], 2);
        rs1[i] += __shfl_xor_sync(0xffffffffu, rs1[i], 1);
        rs1[i] += __shfl_xor_sync(0xffffffffu, rs1[i], 2);
    }
    if (t == 0) {
#pragma unroll
        for (int i = 0; i < 4; ++i) {
            red[wc * 128 + wr * 64 + i * 16 + g]     = rs0[i];
            red[wc * 128 + wr * 64 + i * 16 + g + 8] = rs1[i];
        }
    }
    __syncthreads();
    if (tid < 128) {
        float s = red[tid] + red[128 + tid] + red[256 + tid] + red[384 + tid];
        PS[((size_t)bh * SEQ_ + by * 128 + tid) * 16 + bx] = s;
    }
}

// ---------------------------------------------------------------------------
// invl[row] = 1 / sum of 16 partials
// ---------------------------------------------------------------------------
__global__ void __launch_bounds__(256)
inv_reduce_kernel(const float* __restrict__ PS, float* __restrict__ INV)
{
    const int i = blockIdx.x * 256 + threadIdx.x;
    const float4* p = (const float4*)(PS + (size_t)i * 16);
    float4 a = p[0], b = p[1], c = p[2], d = p[3];
    float s = (a.x + a.y + a.z + a.w) + (b.x + b.y + b.z + b.w)
            + (c.x + c.y + c.z + c.w) + (d.x + d.y + d.z + d.w);
    INV[i] = 1.0f / s;
}

// ---------------------------------------------------------------------------
// Context fused (fp16 mma): per CTA = (bh, 128-row strip). K=2048, BK=64.
// Stream fp16 E -> P fp32 gmem (attn output) + fp16 Ps SMEM; ctx += P@VT^T.
// LDH=72. 8 warps (2 row x 4 col; WN=16). 32 iterations.
// ---------------------------------------------------------------------------
__global__ void __launch_bounds__(256)
ctx_fused_kernel(const __half* __restrict__ E, const float* __restrict__ INV,
                 const __half* __restrict__ VT, float* __restrict__ P,
                 __half* __restrict__ CTX)
{
    constexpr int LDH = 72;
    constexpr int AS_STAGE = 128 * LDH;    // halves
    constexpr int BS_STAGE = 64 * LDH;
    extern __shared__ __half smh[];
    __half* As = smh;                      // 2 stages
    __half* Bs = smh + 2 * AS_STAGE;       // 2 stages
    __shared__ float s_inv[128];

    const int strip = blockIdx.x;
    const int bh = blockIdx.y;
    const int b = bh >> 4, h = bh & 15;
    const int tid = threadIdx.x, lane = tid & 31, warp = tid >> 5;
    const int wr = warp & 1, wc = warp >> 1;
    const int g = lane >> 2, t = lane & 3;

    const __half* Eg = E + ((size_t)bh * SEQ_ + strip * 128) * SEQ_;
    float*        Pg = P + ((size_t)bh * SEQ_ + strip * 128) * SEQ_;
    const __half* Vg = VT + (size_t)bh * HDIM_ * SEQ_;
    __half*       Cg = CTX + ((size_t)(b * SEQ_) + strip * 128) * HIDDEN_ + h * HDIM_;

    if (tid < 128) s_inv[tid] = INV[(size_t)bh * SEQ_ + strip * 128 + tid];

    // A tile per kt: 128 rows x 64 halves = 1024 chunks(8h); 4/thread
    uint4 cur[4];
    auto ldgA = [&](int kt, uint4* dst) {
#pragma unroll
        for (int i = 0; i < 4; ++i) {
            int id = tid + i * 256;
            int r = id >> 3, c8 = id & 7;
            dst[i] = ld_cs_v4u(Eg + (size_t)r * SEQ_ + kt * 64 + c8 * 8);
        }
    };
    auto loadB = [&](int kt) {             // 64 d-rows x 64 halves = 512 chunks
        __half* Bd = Bs + (kt & 1) * BS_STAGE;
#pragma unroll
        for (int i = 0; i < 2; ++i) {
            int id = tid + i * 256;
            int r = id >> 3, c8 = id & 7;
            cp_async16(smem_u32(Bd + r * LDH + c8 * 8), Vg + (size_t)r * SEQ_ + kt * 64 + c8 * 8);
        }
        cp_commit();
    };
    auto procA = [&](int kt, uint4* v) {
        __half* Ad = As + (kt & 1) * AS_STAGE;
#pragma unroll
        for (int i = 0; i < 4; ++i) {
            int id = tid + i * 256;
            int r = id >> 3, c8 = id & 7;
            const float inv = s_inv[r];
            float2 f0 = __half22float2(*(__half2*)&v[i].x);
            float2 f1 = __half22float2(*(__half2*)&v[i].y);
            float2 f2 = __half22float2(*(__half2*)&v[i].z);
            float2 f3 = __half22float2(*(__half2*)&v[i].w);
            float p0 = f0.x * inv, p1 = f0.y * inv;
            float p2 = f1.x * inv, p3 = f1.y * inv;
            float p4 = f2.x * inv, p5 = f2.y * inv;
            float p6 = f3.x * inv, p7 = f3.y * inv;
            float* pd = Pg + (size_t)r * SEQ_ + kt * 64 + c8 * 8;
            st_cs_v4f(pd,     make_float4(p0, p1, p2, p3));
            st_cs_v4f(pd + 4, make_float4(p4, p5, p6, p7));
            __half2 q0 = __floats2half2_rn(p0, p1);
            __half2 q1 = __floats2half2_rn(p2, p3);
            __half2 q2 = __floats2half2_rn(p4, p5);
            __half2 q3 = __floats2half2_rn(p6, p7);
            uint4 o;
            o.x = *(uint32_t*)&q0; o.y = *(uint32_t*)&q1;
            o.z = *(uint32_t*)&q2; o.w = *(uint32_t*)&q3;
            *(uint4*)(Ad + r * LDH + c8 * 8) = o;    // (72r+8c)*2 B: 16-aligned
        }
    };

    float ctx[4][2][4];
#pragma unroll
    for (int i = 0; i < 4; ++i)
#pragma unroll
        for (int j = 0; j < 2; ++j)
#pragma unroll
            for (int q = 0; q < 4; ++q) ctx[i][j][q] = 0.f;

    ldgA(0, cur);
    loadB(0);
    __syncthreads();               // s_inv visible

    for (int kt = 0; kt < 32; ++kt) {
        procA(kt, cur);
        cp_wait_group<0>();        // B tile kt landed
        __syncthreads();           // STS visible; mma kt-1 done everywhere
        if (kt + 1 < 32) {
            ldgA(kt + 1, cur);
            loadB(kt + 1);
        }
        const __half* Ab = As + (kt & 1) * AS_STAGE + (wr * 64) * LDH;
        const __half* Bb = Bs + (kt & 1) * BS_STAGE + (wc * 16) * LDH;
#pragma unroll
        for (int s = 0; s < 4; ++s) {        // 64 keys = 4 x k16
            const int k0 = s * 16;
            uint32_t a[4][4], bf[2][2];
#pragma unroll
            for (int i = 0; i < 4; ++i) {
                const __half* ap = Ab + (i * 16 + g) * LDH + k0 + 2 * t;
                a[i][0] = *(const uint32_t*)(ap);
                a[i][1] = *(const uint32_t*)(ap + 8 * LDH);
                a[i][2] = *(const uint32_t*)(ap + 8);
                a[i][3] = *(const uint32_t*)(ap + 8 * LDH + 8);
            }
#pragma unroll
            for (int j = 0; j < 2; ++j) {
                const __half* bp = Bb + (j * 8 + g) * LDH + k0 + 2 * t;
                bf[j][0] = *(const uint32_t*)(bp);
                bf[j][1] = *(const uint32_t*)(bp + 8);
            }
#pragma unroll
            for (int i = 0; i < 4; ++i)
#pragma unroll
                for (int j = 0; j < 2; ++j)
                    mma16816(ctx[i][j], a[i], bf[j]);
        }
        __syncthreads();
    }

    // write ctx as fp16 (feeds out-projection)
#pragma unroll
    for (int i = 0; i < 4; ++i) {
        const int rA = wr * 64 + i * 16 + g;
#pragma unroll
        for (int j = 0; j < 2; ++j) {
            const int c = wc * 16 + j * 8 + 2 * t;
            __half2 h0 = __floats2half2_rn(ctx[i][j][0], ctx[i][j][1]);
            __half2 h1 = __floats2half2_rn(ctx[i][j][2], ctx[i][j][3]);
            *(__half2*)(Cg + (size_t)rA * HIDDEN_ + c)       = h0;
            *(__half2*)(Cg + (size_t)(rA + 8) * HIDDEN_ + c) = h1;
        }
    }
}

// ---------------------------------------------------------------------------
// Residual + LayerNorm (fp32)
// ---------------------------------------------------------------------------
__global__ void __launch_bounds__(256)
ln_kernel(const float* __restrict__ o, const float* __restrict__ resid,
          const float* __restrict__ gamma, const float* __restrict__ beta,
          float* __restrict__ out)
{
    __shared__ float red1[8], red2[8];
    __shared__ float bmean, binv;

    const size_t row = blockIdx.x;
    const int tid = threadIdx.x;
    const int lane = tid & 31, wid = tid >> 5;
    const float* po = o + row * HIDDEN_;
    const float* pr = resid + row * HIDDEN_;

    float x[4];
    float s = 0.0f, s2 = 0.0f;
#pragma unroll
    for (int u = 0; u < 4; ++u) {
        const int idx = tid + 256 * u;
        x[u] = po[idx] + pr[idx];
        s += x[u];
        s2 += x[u] * x[u];
    }
#pragma unroll
    for (int of = 16; of; of >>= 1) {
        s  += __shfl_xor_sync(0xffffffffu, s,  of);
        s2 += __shfl_xor_sync(0xffffffffu, s2, of);
    }
    if (lane == 0) { red1[wid] = s; red2[wid] = s2; }
    __syncthreads();
    if (wid == 0) {
        float t1 = (lane < 8) ? red1[lane] : 0.0f;
        float t2 = (lane < 8) ? red2[lane] : 0.0f;
#pragma unroll
        for (int of = 16; of; of >>= 1) {
            t1 += __shfl_xor_sync(0xffffffffu, t1, of);
            t2 += __shfl_xor_sync(0xffffffffu, t2, of);
        }
        if (lane == 0) {
            const float mean = t1 * (1.0f / HIDDEN_);
            const float var  = t2 * (1.0f / HIDDEN_) - mean * mean;
            bmean = mean;
            binv  = rsqrtf(var + 1e-5f);
        }
    }
    __syncthreads();
    const float mean = bmean, inv = binv;
#pragma unroll
    for (int u = 0; u < 4; ++u) {
        const int idx = tid + 256 * u;
        out[row * HIDDEN_ + idx] = (x[u] - mean) * inv * gamma[idx] + beta[idx];
    }
}

// ---------------------------------------------------------------------------
static const int DSM_GEMM16   = 4 * 128 * 72 * 2;                  // 73728
static const int DSM_SCORES16 = 2 * 128 * 72 * 2;                  // 36864
static const int DSM_CTX16    = (2 * 128 * 72 + 2 * 64 * 72) * 2;  // 55296

extern "C" void kernel_launch(void* const* d_in, const int* in_sizes, int n_in,
                              void* d_out, int out_size)
{
    const float* query = (const float*)d_in[0];
    const float* key_  = (const float*)d_in[1];
    const float* value = (const float*)d_in[2];
    const float* Wq = (const float*)d_in[3];
    const float* bq = (const float*)d_in[4];
    const float* Wk = (const float*)d_in[5];
    const float* bk = (const float*)d_in[6];
    const float* Wv = (const float*)d_in[7];
    const float* bv = (const float*)d_in[8];
    const float* Wo = (const float*)d_in[9];
    const float* bo = (const float*)d_in[10];
    const float* gamma = (const float*)d_in[11];
    const float* beta  = (const float*)d_in[12];
    const float* temp  = (const float*)d_in[13];

    cudaFuncSetAttribute(gemm16_qkv, cudaFuncAttributeMaxDynamicSharedMemorySize, DSM_GEMM16);
    cudaFuncSetAttribute(gemm16_o,   cudaFuncAttributeMaxDynamicSharedMemorySize, DSM_GEMM16);
    cudaFuncSetAttribute(scores_exp_kernel, cudaFuncAttributeMaxDynamicSharedMemorySize, DSM_SCORES16);
    cudaFuncSetAttribute(ctx_fused_kernel,  cudaFuncAttributeMaxDynamicSharedMemorySize, DSM_CTX16);

    float* out_ln = (float*)d_out;
    __half *pQin, *pKin, *pVin, *pW16, *pQ16, *pK16, *pV16, *pVT16, *pCtx16, *pE;
    float *pO, *pPS, *pINV, *pP;
    cudaGetSymbolAddress((void**)&pQin,  g_q16in);
    cudaGetSymbolAddress((void**)&pKin,  g_k16in);
    cudaGetSymbolAddress((void**)&pVin,  g_v16in);
    cudaGetSymbolAddress((void**)&pW16,  g_W16);
    cudaGetSymbolAddress((void**)&pQ16,  g_Q16);
    cudaGetSymbolAddress((void**)&pK16,  g_K16);
    cudaGetSymbolAddress((void**)&pV16,  g_V16);
    cudaGetSymbolAddress((void**)&pVT16, g_VT16);
    cudaGetSymbolAddress((void**)&pCtx16,g_ctx16);
    cudaGetSymbolAddress((void**)&pE,    g_E);
    cudaGetSymbolAddress((void**)&pO,    g_o);
    cudaGetSymbolAddress((void**)&pPS,   g_PS);
    cudaGetSymbolAddress((void**)&pINV,  g_INV);
    if ((long long)out_size >= LN_N + ATT_N) {
        pP = out_ln + LN_N;           // attn_weights are part of the output
    } else {
        cudaGetSymbolAddress((void**)&pP, g_Pfb);
    }
    const int WN = HIDDEN_ * HIDDEN_;

    // --- fp32 -> fp16 conversions (one batched launch)
    {
        Cvt7 c;
        c.src[0] = query; c.dst[0] = pQin;          c.n8[0] = (MTOT_ * HIDDEN_) / 8;
        c.src[1] = key_;  c.dst[1] = pKin;          c.n8[1] = (MTOT_ * HIDDEN_) / 8;
        c.src[2] = value; c.dst[2] = pVin;          c.n8[2] = (MTOT_ * HIDDEN_) / 8;
        c.src[3] = Wq;    c.dst[3] = pW16 + 0ll*WN; c.n8[3] = WN / 8;
        c.src[4] = Wk;    c.dst[4] = pW16 + 1ll*WN; c.n8[4] = WN / 8;
        c.src[5] = Wv;    c.dst[5] = pW16 + 2ll*WN; c.n8[5] = WN / 8;
        c.src[6] = Wo;    c.dst[6] = pW16 + 3ll*WN; c.n8[6] = WN / 8;
        dim3 g((MTOT_ * HIDDEN_ / 8 + 255) / 256, 7, 1);
        cvt_kernel<<<g, 256>>>(c);
    }

    // --- Merged Q/K/V projections (fp16)
    {
        QKV16 p;
        p.A[0] = pQin; p.A[1] = pKin; p.A[2] = pVin;
        p.W[0] = pW16; p.W[1] = pW16 + 1ll*WN; p.W[2] = pW16 + 2ll*WN;
        p.bias[0] = bq; p.bias[1] = bk; p.bias[2] = bv;
        p.C[0] = pQ16; p.C[1] = pK16; p.C[2] = pV16;
        dim3 g(HIDDEN_ / 128, MTOT_ / 128, 3);
        gemm16_qkv<<<g, 256, DSM_GEMM16>>>(p);
    }

    // --- VT transpose (fp16)
    {
        dim3 g(SEQ_ / 32, HDIM_ / 32, BATCH_ * HEADS_);
        transpose_v_kernel<<<g, 256>>>(pV16, pVT16);
    }

    // --- Scores + exp (h2exp2, coalesced fp16 E) + partial sums
    {
        dim3 g(SEQ_ / 128, SEQ_ / 128, BATCH_ * HEADS_);
        scores_exp_kernel<<<g, 256, DSM_SCORES16>>>(pQ16, pK16, pE, pPS, temp);
    }

    // --- invl
    inv_reduce_kernel<<<NROWS_ / 256, 256>>>(pPS, pINV);

    // --- Context fused: P write (fp32) + ctx mma (fp16, BK=64)
    {
        dim3 g(SEQ_ / 128, BATCH_ * HEADS_, 1);
        ctx_fused_kernel<<<g, 256, DSM_CTX16>>>(pE, pINV, pVT16, pP, pCtx16);
    }

    // --- Output projection: o = ctx @ Wo^T + bo (fp32 out)
    {
        dim3 g(HIDDEN_ / 128, MTOT_ / 128, 1);
        gemm16_o<<<g, 256, DSM_GEMM16>>>(pCtx16, pW16 + 3ll*WN, bo, pO);
    }

    // --- Residual + LayerNorm
    ln_kernel<<<(unsigned)MTOT_, 256>>>(pO, query, gamma, beta, out_ln);
}